// round 1
// baseline (speedup 1.0000x reference)
#include <cuda_runtime.h>
#include <cuda_bf16.h>
#include <math.h>

#define Bn    4
#define Nn    2048
#define DIMn  512
#define HEADSn 8
#define DHn   64
#define HIDn  512

// Scratch (allocation-free rule: device globals)
__device__ float g_qkv[Bn * Nn * 3 * HIDn];   // (B,N,1536): q|k|v
__device__ float g_o  [Bn * Nn * HIDn];       // (B,N,512) attention output (heads interleaved)
__device__ int   g_focus[Bn];

// ---------------------------------------------------------------------------
// Mask decode: focus_present_mask dtype on device is ambiguous (bool / int32 /
// float32 serialization). Disambiguate by bit pattern. All-zero is consistent
// under every interpretation.
// ---------------------------------------------------------------------------
__global__ void decode_mask_kernel(const unsigned char* __restrict__ p) {
    unsigned int w[4];
#pragma unroll
    for (int i = 0; i < 4; i++) w[i] = ((const unsigned int*)p)[i];

    bool allF = true, allI = true, anyNZ = false;
#pragma unroll
    for (int i = 0; i < 4; i++) {
        if (w[i] != 0u) anyNZ = true;
        if (w[i] != 0u && w[i] != 0x3F800000u) allF = false;
        if (w[i] > 1u) allI = false;
    }
    if (anyNZ && allF) {            // float32 0.0/1.0
        for (int i = 0; i < 4; i++) g_focus[i] = (w[i] == 0x3F800000u);
    } else if (allI) {              // int32 0/1 (also covers bool [x,0,0,0] w/ zeroed tail)
        for (int i = 0; i < 4; i++) g_focus[i] = (int)w[i];
    } else {                        // 1-byte bool
        for (int i = 0; i < 4; i++) g_focus[i] = p[i] ? 1 : 0;
    }
}

// ---------------------------------------------------------------------------
// Classic 128x128x8 fp32 SGEMM, 256 threads, 8x8 per thread, vectorized.
// A: MxK row-major, B: KxN row-major, C: MxN. All dims divide tile sizes.
// ---------------------------------------------------------------------------
__global__ void __launch_bounds__(256) sgemm_kernel(
    int M, int N, int K,
    const float* __restrict__ A, const float* __restrict__ B, float* __restrict__ C)
{
    constexpr int BM = 128, BN = 128, BK = 8, TM = 8, TN = 8;
    __shared__ float As[BK][BM];   // transposed A tile
    __shared__ float Bs[BK][BN];

    const int tid  = threadIdx.x;
    const int brow = blockIdx.y * BM;
    const int bcol = blockIdx.x * BN;
    const int tRow = (tid / 16) * TM;
    const int tCol = (tid % 16) * TN;
    const int aRow = tid >> 1, aCol = (tid & 1) * 4;     // 128x8 tile, float4/thread
    const int bRow = tid >> 5, bCol = (tid & 31) * 4;    // 8x128 tile, float4/thread

    float acc[TM][TN];
#pragma unroll
    for (int i = 0; i < TM; i++)
#pragma unroll
        for (int j = 0; j < TN; j++) acc[i][j] = 0.f;

    const float* Ap = A + (size_t)(brow + aRow) * K + aCol;
    const float* Bp = B + (size_t)bRow * N + bcol + bCol;

    for (int k0 = 0; k0 < K; k0 += BK) {
        float4 a4 = *(const float4*)(Ap + k0);
        As[aCol + 0][aRow] = a4.x;
        As[aCol + 1][aRow] = a4.y;
        As[aCol + 2][aRow] = a4.z;
        As[aCol + 3][aRow] = a4.w;
        *(float4*)(&Bs[bRow][bCol]) = *(const float4*)(Bp + (size_t)k0 * N);
        __syncthreads();

#pragma unroll
        for (int k = 0; k < BK; k++) {
            float regM[TM], regN[TN];
            *(float4*)(regM)     = *(const float4*)(&As[k][tRow]);
            *(float4*)(regM + 4) = *(const float4*)(&As[k][tRow + 4]);
            *(float4*)(regN)     = *(const float4*)(&Bs[k][tCol]);
            *(float4*)(regN + 4) = *(const float4*)(&Bs[k][tCol + 4]);
#pragma unroll
            for (int i = 0; i < TM; i++)
#pragma unroll
                for (int j = 0; j < TN; j++)
                    acc[i][j] = fmaf(regM[i], regN[j], acc[i][j]);
        }
        __syncthreads();
    }

#pragma unroll
    for (int i = 0; i < TM; i++) {
        float* Cp = C + (size_t)(brow + tRow + i) * N + bcol + tCol;
        *(float4*)(Cp)     = make_float4(acc[i][0], acc[i][1], acc[i][2], acc[i][3]);
        *(float4*)(Cp + 4) = make_float4(acc[i][4], acc[i][5], acc[i][6], acc[i][7]);
    }
}

// ---------------------------------------------------------------------------
// Flash attention, fp32. One block = 64 queries of one (b,h). 256 threads in a
// 16x16 grid, each owning a 4x4 subtile. Online softmax with pos_bias.
// Focus batches: softmax == eye exactly => out = v (pure copy).
// qkv layout: [b][n][0:512]=q, [512:1024]=k, [1024:1536]=v; head h = cols h*64..h*64+63.
// Output g_o layout: [b][n][h*64+d]  (== transpose(0,2,1,3).reshape).
// ---------------------------------------------------------------------------
__global__ void __launch_bounds__(256) flash_kernel(
    const float* __restrict__ qkv, const float* __restrict__ pos_bias, float* __restrict__ O)
{
    const int qt = blockIdx.x;      // 0..31
    const int h  = blockIdx.y;
    const int b  = blockIdx.z;
    const int tid = threadIdx.x;
    const int q0 = qt * 64;

    if (g_focus[b]) {
        // out == v exactly (exp(-FLT_MAX shift) underflows to 0 off-diagonal)
#pragma unroll
        for (int it = 0; it < 4; it++) {
            int lin = tid + it * 256;              // 0..1023
            int r   = lin >> 4;
            int c4  = (lin & 15) * 4;
            const float4 v = *(const float4*)(qkv + (size_t)(b * Nn + q0 + r) * (3 * HIDn)
                                              + 2 * HIDn + h * DHn + c4);
            *(float4*)(O + (size_t)(b * Nn + q0 + r) * HIDn + h * DHn + c4) = v;
        }
        return;
    }

    extern __shared__ float sm[];
    float (*Qs)[65] = (float (*)[65])(sm);                       // 64x65 (padded)
    float (*Ks)[65] = (float (*)[65])(sm + 64 * 65);             // 64x65 (padded)
    float (*Vs)[64] = (float (*)[64])(sm + 2 * 64 * 65);         // 64x64
    float (*Ps)[64] = (float (*)[64])(sm + 2 * 64 * 65 + 64 * 64);

    const int tx = tid & 15;
    const int ty = tid >> 4;
    const float scale = 0.125f;     // 64^-0.5

    // Load Q tile (scaled)
#pragma unroll
    for (int it = 0; it < 4; it++) {
        int lin = tid + it * 256;
        int r   = lin >> 4;
        int c4  = (lin & 15) * 4;
        float4 q4 = *(const float4*)(qkv + (size_t)(b * Nn + q0 + r) * (3 * HIDn) + h * DHn + c4);
        Qs[r][c4 + 0] = q4.x * scale;
        Qs[r][c4 + 1] = q4.y * scale;
        Qs[r][c4 + 2] = q4.z * scale;
        Qs[r][c4 + 3] = q4.w * scale;
    }

    float m[4], l[4], o[4][4];
#pragma unroll
    for (int i = 0; i < 4; i++) {
        m[i] = -1e30f; l[i] = 0.f;
#pragma unroll
        for (int j = 0; j < 4; j++) o[i][j] = 0.f;
    }

    const float* pb = pos_bias + (size_t)h * Nn * Nn;

    for (int kt = 0; kt < Nn / 64; kt++) {
        const int k0 = kt * 64;
        __syncthreads();  // prior PV done reading Vs; Q visible on first iter

        // Load K,V tiles
#pragma unroll
        for (int it = 0; it < 4; it++) {
            int lin = tid + it * 256;
            int r   = lin >> 4;
            int c4  = (lin & 15) * 4;
            const float* base = qkv + (size_t)(b * Nn + k0 + r) * (3 * HIDn) + h * DHn + c4;
            float4 k4 = *(const float4*)(base + HIDn);
            Ks[r][c4 + 0] = k4.x; Ks[r][c4 + 1] = k4.y;
            Ks[r][c4 + 2] = k4.z; Ks[r][c4 + 3] = k4.w;
            *(float4*)(&Vs[r][c4]) = *(const float4*)(base + 2 * HIDn);
        }
        __syncthreads();

        // S = Q @ K^T (4x4 per thread)
        float s[4][4];
#pragma unroll
        for (int i = 0; i < 4; i++)
#pragma unroll
            for (int j = 0; j < 4; j++) s[i][j] = 0.f;
#pragma unroll
        for (int k = 0; k < 64; k++) {
            float qr[4], kc[4];
#pragma unroll
            for (int i = 0; i < 4; i++) qr[i] = Qs[ty * 4 + i][k];
#pragma unroll
            for (int j = 0; j < 4; j++) kc[j] = Ks[tx * 4 + j][k];
#pragma unroll
            for (int i = 0; i < 4; i++)
#pragma unroll
                for (int j = 0; j < 4; j++)
                    s[i][j] = fmaf(qr[i], kc[j], s[i][j]);
        }

        // + pos_bias
#pragma unroll
        for (int i = 0; i < 4; i++) {
            float4 bb = *(const float4*)(pb + (size_t)(q0 + ty * 4 + i) * Nn + k0 + tx * 4);
            s[i][0] += bb.x; s[i][1] += bb.y; s[i][2] += bb.z; s[i][3] += bb.w;
        }

        // Online softmax per row (16 tx-threads per row are a contiguous 16-lane group)
#pragma unroll
        for (int i = 0; i < 4; i++) {
            float rmax = fmaxf(fmaxf(s[i][0], s[i][1]), fmaxf(s[i][2], s[i][3]));
#pragma unroll
            for (int off = 8; off >= 1; off >>= 1)
                rmax = fmaxf(rmax, __shfl_xor_sync(0xffffffffu, rmax, off));
            float mn   = fmaxf(m[i], rmax);
            float corr = __expf(m[i] - mn);
            float rsum = 0.f;
#pragma unroll
            for (int j = 0; j < 4; j++) { s[i][j] = __expf(s[i][j] - mn); rsum += s[i][j]; }
#pragma unroll
            for (int off = 8; off >= 1; off >>= 1)
                rsum += __shfl_xor_sync(0xffffffffu, rsum, off);
            l[i] = l[i] * corr + rsum;
            m[i] = mn;
#pragma unroll
            for (int j = 0; j < 4; j++) o[i][j] *= corr;
#pragma unroll
            for (int j = 0; j < 4; j++) Ps[ty * 4 + i][tx * 4 + j] = s[i][j];
        }
        __syncthreads();

        // O += P @ V
#pragma unroll
        for (int k = 0; k < 64; k++) {
            float pv[4], vv[4];
#pragma unroll
            for (int i = 0; i < 4; i++) pv[i] = Ps[ty * 4 + i][k];
#pragma unroll
            for (int j = 0; j < 4; j++) vv[j] = Vs[k][tx * 4 + j];
#pragma unroll
            for (int i = 0; i < 4; i++)
#pragma unroll
                for (int j = 0; j < 4; j++)
                    o[i][j] = fmaf(pv[i], vv[j], o[i][j]);
        }
    }

    // Normalize + store
#pragma unroll
    for (int i = 0; i < 4; i++) {
        float inv = 1.f / l[i];
        float* op = O + (size_t)(b * Nn + q0 + ty * 4 + i) * HIDn + h * DHn + tx * 4;
        op[0] = o[i][0] * inv; op[1] = o[i][1] * inv;
        op[2] = o[i][2] * inv; op[3] = o[i][3] * inv;
    }
}

// ---------------------------------------------------------------------------
extern "C" void kernel_launch(void* const* d_in, const int* in_sizes, int n_in,
                              void* d_out, int out_size)
{
    const float*         x        = (const float*)d_in[0];   // (4,2048,512)
    const float*         pos_bias = (const float*)d_in[1];   // (8,2048,2048)
    const unsigned char* maskp    = (const unsigned char*)d_in[2];
    const float*         w_qkv    = (const float*)d_in[3];   // (512,1536)
    const float*         w_out    = (const float*)d_in[4];   // (512,512)
    float*               out      = (float*)d_out;           // (4,2048,512)

    float *qkv_ptr, *o_ptr;
    cudaGetSymbolAddress((void**)&qkv_ptr, g_qkv);
    cudaGetSymbolAddress((void**)&o_ptr,   g_o);

    const int flash_smem = (2 * 64 * 65 + 2 * 64 * 64) * (int)sizeof(float); // 66048 B
    cudaFuncSetAttribute(flash_kernel, cudaFuncAttributeMaxDynamicSharedMemorySize, flash_smem);

    decode_mask_kernel<<<1, 1>>>(maskp);

    // qkv = x @ w_qkv : (8192,512) x (512,1536)
    sgemm_kernel<<<dim3(1536 / 128, 8192 / 128), 256>>>(8192, 1536, 512, x, w_qkv, qkv_ptr);

    // attention (fused flash, focus fast path)
    flash_kernel<<<dim3(Nn / 64, HEADSn, Bn), 256, flash_smem>>>(qkv_ptr, pos_bias, o_ptr);

    // out = O @ w_out : (8192,512) x (512,512)
    sgemm_kernel<<<dim3(512 / 128, 8192 / 128), 256>>>(8192, 512, 512, o_ptr, w_out, out);
}

// round 2
// speedup vs baseline: 1.7052x; 1.7052x over previous
#include <cuda_runtime.h>
#include <cuda_bf16.h>
#include <math.h>
#include <stdint.h>

#define Bn    4
#define Nn    2048
#define DIMn  512
#define HEADSn 8
#define DHn   64
#define HIDn  512

// Scratch (allocation-free rule: device globals)
__device__ float g_qkv[Bn * Nn * 3 * HIDn];   // (B,N,1536): q|k|v
__device__ float g_o  [Bn * Nn * HIDn];       // (B,N,512) attention out, heads interleaved
__device__ int   g_focus[Bn];

// ---------------------------------------------------------------------------
// tf32 helpers
// ---------------------------------------------------------------------------
__device__ __forceinline__ float f2tf(float f) {
    uint32_t u;
    asm("cvt.rna.tf32.f32 %0, %1;" : "=r"(u) : "f"(f));
    return __uint_as_float(u);
}

// D += A(16x8,row) * B(8x8,col), tf32 inputs, f32 accum
__device__ __forceinline__ void mma8(float* d, const uint32_t* a, uint32_t b0, uint32_t b1) {
    asm volatile(
        "mma.sync.aligned.m16n8k8.row.col.f32.tf32.tf32.f32 "
        "{%0,%1,%2,%3}, {%4,%5,%6,%7}, {%8,%9}, {%0,%1,%2,%3};"
        : "+f"(d[0]), "+f"(d[1]), "+f"(d[2]), "+f"(d[3])
        : "r"(a[0]), "r"(a[1]), "r"(a[2]), "r"(a[3]), "r"(b0), "r"(b1));
}

// ---------------------------------------------------------------------------
// Mask decode (dtype-ambiguous bool mask)
// ---------------------------------------------------------------------------
__global__ void decode_mask_kernel(const unsigned char* __restrict__ p) {
    unsigned int w[4];
#pragma unroll
    for (int i = 0; i < 4; i++) w[i] = ((const unsigned int*)p)[i];
    bool allF = true, allI = true, anyNZ = false;
#pragma unroll
    for (int i = 0; i < 4; i++) {
        if (w[i] != 0u) anyNZ = true;
        if (w[i] != 0u && w[i] != 0x3F800000u) allF = false;
        if (w[i] > 1u) allI = false;
    }
    if (anyNZ && allF)      for (int i = 0; i < 4; i++) g_focus[i] = (w[i] == 0x3F800000u);
    else if (allI)          for (int i = 0; i < 4; i++) g_focus[i] = (int)w[i];
    else                    for (int i = 0; i < 4; i++) g_focus[i] = p[i] ? 1 : 0;
}

// ---------------------------------------------------------------------------
// tf32 tensor-core GEMM: C(MxN) = A(MxK) @ B(KxN), row-major, 128x128x32 tiles.
// 256 threads = 8 warps (4m x 2n), warp tile 32x64 via m16n8k8.
// ---------------------------------------------------------------------------
__global__ void __launch_bounds__(256) gemm_tf32_kernel(
    int M, int N, int K,
    const float* __restrict__ A, const float* __restrict__ B, float* __restrict__ C)
{
    __shared__ float As[128][36];   // [m][k], stride 36 -> conflict-free frags
    __shared__ float Bs[32][136];   // [k][n], stride 136 -> conflict-free frags

    const int tid  = threadIdx.x;
    const int lane = tid & 31;
    const int w    = tid >> 5;
    const int wm   = (w >> 1) * 32;
    const int wn   = (w & 1) * 64;
    const int brow = blockIdx.y * 128;
    const int bcol = blockIdx.x * 128;

    float acc[2][8][4];
#pragma unroll
    for (int mt = 0; mt < 2; mt++)
#pragma unroll
        for (int nt = 0; nt < 8; nt++)
#pragma unroll
            for (int i = 0; i < 4; i++) acc[mt][nt][i] = 0.f;

    for (int k0 = 0; k0 < K; k0 += 32) {
        // A tile: 128x32 (1024 float4, 4/thread)
#pragma unroll
        for (int it = 0; it < 4; it++) {
            int lin = tid + it * 256;
            int r = lin >> 3, c4 = (lin & 7) * 4;
            float4 v = *(const float4*)(A + (size_t)(brow + r) * K + k0 + c4);
            *(float4*)(&As[r][c4]) = make_float4(f2tf(v.x), f2tf(v.y), f2tf(v.z), f2tf(v.w));
        }
        // B tile: 32x128
#pragma unroll
        for (int it = 0; it < 4; it++) {
            int lin = tid + it * 256;
            int r = lin >> 5, c4 = (lin & 31) * 4;
            float4 v = *(const float4*)(B + (size_t)(k0 + r) * N + bcol + c4);
            *(float4*)(&Bs[r][c4]) = make_float4(f2tf(v.x), f2tf(v.y), f2tf(v.z), f2tf(v.w));
        }
        __syncthreads();

#pragma unroll
        for (int kc = 0; kc < 4; kc++) {
            uint32_t af[2][4];
            const int c = kc * 8 + (lane & 3);
#pragma unroll
            for (int mt = 0; mt < 2; mt++) {
                int row = wm + mt * 16 + (lane >> 2);
                af[mt][0] = __float_as_uint(As[row][c]);
                af[mt][1] = __float_as_uint(As[row + 8][c]);
                af[mt][2] = __float_as_uint(As[row][c + 4]);
                af[mt][3] = __float_as_uint(As[row + 8][c + 4]);
            }
            const int kr = kc * 8 + (lane & 3);
#pragma unroll
            for (int nt = 0; nt < 8; nt++) {
                int col = wn + nt * 8 + (lane >> 2);
                uint32_t b0 = __float_as_uint(Bs[kr][col]);
                uint32_t b1 = __float_as_uint(Bs[kr + 4][col]);
                mma8(acc[0][nt], af[0], b0, b1);
                mma8(acc[1][nt], af[1], b0, b1);
            }
        }
        __syncthreads();
    }

#pragma unroll
    for (int mt = 0; mt < 2; mt++) {
#pragma unroll
        for (int nt = 0; nt < 8; nt++) {
            int r = brow + wm + mt * 16 + (lane >> 2);
            int c = bcol + wn + nt * 8 + (lane & 3) * 2;
            *(float2*)(C + (size_t)r * N + c)       = make_float2(acc[mt][nt][0], acc[mt][nt][1]);
            *(float2*)(C + (size_t)(r + 8) * N + c) = make_float2(acc[mt][nt][2], acc[mt][nt][3]);
        }
    }
}

// ---------------------------------------------------------------------------
// Flash attention, tf32 tensor cores. Block = 64 q rows of one (b,h), 128 thr
// = 4 warps; warp owns 16 q rows. 64-key tiles, online softmax in registers.
// Focus batches: out == v exactly (copy).
// ---------------------------------------------------------------------------
#define FLASH_SMEM ((64 * 68 * 3 + 64 * 72) * 4)

__global__ void __launch_bounds__(128) flash_tf32_kernel(
    const float* __restrict__ qkv, const float* __restrict__ pos_bias, float* __restrict__ O)
{
    const int qt = blockIdx.x, h = blockIdx.y, b = blockIdx.z;
    const int tid = threadIdx.x, lane = tid & 31, w = tid >> 5;
    const int q0 = qt * 64;

    if (g_focus[b]) {
#pragma unroll
        for (int it = 0; it < 8; it++) {
            int lin = tid + it * 128;
            int r = lin >> 4, c4 = (lin & 15) * 4;
            const float4 v = *(const float4*)(qkv + (size_t)(b * Nn + q0 + r) * (3 * HIDn)
                                              + 2 * HIDn + h * DHn + c4);
            *(float4*)(O + (size_t)(b * Nn + q0 + r) * HIDn + h * DHn + c4) = v;
        }
        return;
    }

    extern __shared__ float sm[];
    float (*Qs)[68] = (float (*)[68])(sm);                         // 64x68
    float (*Ks)[68] = (float (*)[68])(sm + 64 * 68);               // 64x68
    float (*Vs)[72] = (float (*)[72])(sm + 2 * 64 * 68);           // 64x72
    float (*Ps)[68] = (float (*)[68])(sm + 2 * 64 * 68 + 64 * 72); // 64x68

    const float scale = 0.125f;

    // Load Q (scaled, tf32)
#pragma unroll
    for (int it = 0; it < 8; it++) {
        int lin = tid + it * 128;
        int r = lin >> 4, c4 = (lin & 15) * 4;
        float4 q4 = *(const float4*)(qkv + (size_t)(b * Nn + q0 + r) * (3 * HIDn) + h * DHn + c4);
        *(float4*)(&Qs[r][c4]) = make_float4(f2tf(q4.x * scale), f2tf(q4.y * scale),
                                             f2tf(q4.z * scale), f2tf(q4.w * scale));
    }
    __syncthreads();

    // Q fragments in registers (A operand, reused every k-tile)
    uint32_t aq[8][4];
    {
        const int r0 = w * 16 + (lane >> 2);
#pragma unroll
        for (int kc = 0; kc < 8; kc++) {
            int c = kc * 8 + (lane & 3);
            aq[kc][0] = __float_as_uint(Qs[r0][c]);
            aq[kc][1] = __float_as_uint(Qs[r0 + 8][c]);
            aq[kc][2] = __float_as_uint(Qs[r0][c + 4]);
            aq[kc][3] = __float_as_uint(Qs[r0 + 8][c + 4]);
        }
    }

    float o[8][4];
#pragma unroll
    for (int nt = 0; nt < 8; nt++)
#pragma unroll
        for (int i = 0; i < 4; i++) o[nt][i] = 0.f;
    float m0 = -1e30f, m1 = -1e30f, l0 = 0.f, l1 = 0.f;

    const float* pbbase = pos_bias + ((size_t)h * Nn + (q0 + w * 16 + (lane >> 2))) * Nn
                          + 2 * (lane & 3);

    for (int kt = 0; kt < Nn / 64; kt++) {
        const int k0 = kt * 64;
        __syncthreads();   // prior iter done reading Ks/Vs

        // Load K, V tiles (tf32)
#pragma unroll
        for (int it = 0; it < 8; it++) {
            int lin = tid + it * 128;
            int r = lin >> 4, c4 = (lin & 15) * 4;
            const float* base = qkv + (size_t)(b * Nn + k0 + r) * (3 * HIDn) + h * DHn + c4;
            float4 kk = *(const float4*)(base + HIDn);
            *(float4*)(&Ks[r][c4]) = make_float4(f2tf(kk.x), f2tf(kk.y), f2tf(kk.z), f2tf(kk.w));
            float4 vv = *(const float4*)(base + 2 * HIDn);
            *(float4*)(&Vs[r][c4]) = make_float4(f2tf(vv.x), f2tf(vv.y), f2tf(vv.z), f2tf(vv.w));
        }
        __syncthreads();

        // S = Q @ K^T
        float s[8][4];
#pragma unroll
        for (int nt = 0; nt < 8; nt++)
#pragma unroll
            for (int i = 0; i < 4; i++) s[nt][i] = 0.f;
#pragma unroll
        for (int kc = 0; kc < 8; kc++) {
            const int d = kc * 8 + (lane & 3);
#pragma unroll
            for (int nt = 0; nt < 8; nt++) {
                int kr = nt * 8 + (lane >> 2);
                uint32_t b0 = __float_as_uint(Ks[kr][d]);
                uint32_t b1 = __float_as_uint(Ks[kr][d + 4]);
                mma8(s[nt], aq[kc], b0, b1);
            }
        }

        // + pos_bias
        const float* pb0 = pbbase + k0;
        const float* pb1 = pb0 + 8 * Nn;
#pragma unroll
        for (int nt = 0; nt < 8; nt++) {
            float2 x0 = *(const float2*)(pb0 + nt * 8);
            float2 x1 = *(const float2*)(pb1 + nt * 8);
            s[nt][0] += x0.x; s[nt][1] += x0.y;
            s[nt][2] += x1.x; s[nt][3] += x1.y;
        }

        // Online softmax (rows lane/4 and lane/4+8; 4-lane groups share a row)
        float rmax0 = -1e30f, rmax1 = -1e30f;
#pragma unroll
        for (int nt = 0; nt < 8; nt++) {
            rmax0 = fmaxf(rmax0, fmaxf(s[nt][0], s[nt][1]));
            rmax1 = fmaxf(rmax1, fmaxf(s[nt][2], s[nt][3]));
        }
#pragma unroll
        for (int off = 1; off <= 2; off <<= 1) {
            rmax0 = fmaxf(rmax0, __shfl_xor_sync(0xffffffffu, rmax0, off));
            rmax1 = fmaxf(rmax1, __shfl_xor_sync(0xffffffffu, rmax1, off));
        }
        float mn0 = fmaxf(m0, rmax0), mn1 = fmaxf(m1, rmax1);
        float corr0 = __expf(m0 - mn0), corr1 = __expf(m1 - mn1);
        float rs0 = 0.f, rs1 = 0.f;
#pragma unroll
        for (int nt = 0; nt < 8; nt++) {
            s[nt][0] = __expf(s[nt][0] - mn0); rs0 += s[nt][0];
            s[nt][1] = __expf(s[nt][1] - mn0); rs0 += s[nt][1];
            s[nt][2] = __expf(s[nt][2] - mn1); rs1 += s[nt][2];
            s[nt][3] = __expf(s[nt][3] - mn1); rs1 += s[nt][3];
        }
#pragma unroll
        for (int off = 1; off <= 2; off <<= 1) {
            rs0 += __shfl_xor_sync(0xffffffffu, rs0, off);
            rs1 += __shfl_xor_sync(0xffffffffu, rs1, off);
        }
        l0 = l0 * corr0 + rs0;  m0 = mn0;
        l1 = l1 * corr1 + rs1;  m1 = mn1;
#pragma unroll
        for (int nt = 0; nt < 8; nt++) {
            o[nt][0] *= corr0; o[nt][1] *= corr0;
            o[nt][2] *= corr1; o[nt][3] *= corr1;
        }

        // P -> smem (tf32); warp-local rows only
        {
            int pr = w * 16 + (lane >> 2);
            int pc = 2 * (lane & 3);
#pragma unroll
            for (int nt = 0; nt < 8; nt++) {
                Ps[pr][nt * 8 + pc]         = f2tf(s[nt][0]);
                Ps[pr][nt * 8 + pc + 1]     = f2tf(s[nt][1]);
                Ps[pr + 8][nt * 8 + pc]     = f2tf(s[nt][2]);
                Ps[pr + 8][nt * 8 + pc + 1] = f2tf(s[nt][3]);
            }
        }
        __syncwarp();

        // O += P @ V
#pragma unroll
        for (int kc = 0; kc < 8; kc++) {
            uint32_t pa[4];
            int pr = w * 16 + (lane >> 2);
            int pcc = kc * 8 + (lane & 3);
            pa[0] = __float_as_uint(Ps[pr][pcc]);
            pa[1] = __float_as_uint(Ps[pr + 8][pcc]);
            pa[2] = __float_as_uint(Ps[pr][pcc + 4]);
            pa[3] = __float_as_uint(Ps[pr + 8][pcc + 4]);
            const int vr = kc * 8 + (lane & 3);
#pragma unroll
            for (int nt = 0; nt < 8; nt++) {
                int vc = nt * 8 + (lane >> 2);
                uint32_t b0 = __float_as_uint(Vs[vr][vc]);
                uint32_t b1 = __float_as_uint(Vs[vr + 4][vc]);
                mma8(o[nt], pa, b0, b1);
            }
        }
    }

    // Normalize + store
    float inv0 = 1.f / l0, inv1 = 1.f / l1;
    int gr = b * Nn + q0 + w * 16 + (lane >> 2);
    float* op = O + (size_t)gr * HIDn + h * DHn + 2 * (lane & 3);
#pragma unroll
    for (int nt = 0; nt < 8; nt++) {
        *(float2*)(op + nt * 8)            = make_float2(o[nt][0] * inv0, o[nt][1] * inv0);
        *(float2*)(op + 8 * HIDn + nt * 8) = make_float2(o[nt][2] * inv1, o[nt][3] * inv1);
    }
}

// ---------------------------------------------------------------------------
extern "C" void kernel_launch(void* const* d_in, const int* in_sizes, int n_in,
                              void* d_out, int out_size)
{
    const float*         x        = (const float*)d_in[0];   // (4,2048,512)
    const float*         pos_bias = (const float*)d_in[1];   // (8,2048,2048)
    const unsigned char* maskp    = (const unsigned char*)d_in[2];
    const float*         w_qkv    = (const float*)d_in[3];   // (512,1536)
    const float*         w_out    = (const float*)d_in[4];   // (512,512)
    float*               out      = (float*)d_out;           // (4,2048,512)

    float *qkv_ptr, *o_ptr;
    cudaGetSymbolAddress((void**)&qkv_ptr, g_qkv);
    cudaGetSymbolAddress((void**)&o_ptr,   g_o);

    cudaFuncSetAttribute(flash_tf32_kernel, cudaFuncAttributeMaxDynamicSharedMemorySize, FLASH_SMEM);

    decode_mask_kernel<<<1, 1>>>(maskp);

    // qkv = x @ w_qkv : (8192,1536,512)
    gemm_tf32_kernel<<<dim3(1536 / 128, 8192 / 128), 256>>>(8192, 1536, 512, x, w_qkv, qkv_ptr);

    // fused flash attention (tf32 mma, focus fast path)
    flash_tf32_kernel<<<dim3(Nn / 64, HEADSn, Bn), 128, FLASH_SMEM>>>(qkv_ptr, pos_bias, o_ptr);

    // out = O @ w_out : (8192,512,512)
    gemm_tf32_kernel<<<dim3(512 / 128, 8192 / 128), 256>>>(8192, 512, 512, o_ptr, w_out, out);
}

// round 3
// speedup vs baseline: 2.6972x; 1.5817x over previous
#include <cuda_runtime.h>
#include <cuda_bf16.h>
#include <math.h>
#include <stdint.h>

#define Bn    4
#define Nn    2048
#define DIMn  512
#define HEADSn 8
#define DHn   64
#define HIDn  512

__device__ float g_qkv[Bn * Nn * 3 * HIDn];   // (B,N,1536): q|k|v
__device__ float g_o  [Bn * Nn * HIDn];       // (B,N,512)
__device__ int   g_focus[Bn];

// ---------------------------------------------------------------------------
__device__ __forceinline__ float f2tf(float f) {
    uint32_t u;
    asm("cvt.rna.tf32.f32 %0, %1;" : "=r"(u) : "f"(f));
    return __uint_as_float(u);
}
__device__ __forceinline__ float ex2f(float x) {
    float r;
    asm("ex2.approx.ftz.f32 %0, %1;" : "=f"(r) : "f"(x));
    return r;
}
__device__ __forceinline__ void mma8(float* d, const uint32_t* a, uint32_t b0, uint32_t b1) {
    asm volatile(
        "mma.sync.aligned.m16n8k8.row.col.f32.tf32.tf32.f32 "
        "{%0,%1,%2,%3}, {%4,%5,%6,%7}, {%8,%9}, {%0,%1,%2,%3};"
        : "+f"(d[0]), "+f"(d[1]), "+f"(d[2]), "+f"(d[3])
        : "r"(a[0]), "r"(a[1]), "r"(a[2]), "r"(a[3]), "r"(b0), "r"(b1));
}

// ---------------------------------------------------------------------------
__global__ void decode_mask_kernel(const unsigned char* __restrict__ p) {
    unsigned int w[4];
#pragma unroll
    for (int i = 0; i < 4; i++) w[i] = ((const unsigned int*)p)[i];
    bool allF = true, allI = true, anyNZ = false;
#pragma unroll
    for (int i = 0; i < 4; i++) {
        if (w[i] != 0u) anyNZ = true;
        if (w[i] != 0u && w[i] != 0x3F800000u) allF = false;
        if (w[i] > 1u) allI = false;
    }
    if (anyNZ && allF)      for (int i = 0; i < 4; i++) g_focus[i] = (w[i] == 0x3F800000u);
    else if (allI)          for (int i = 0; i < 4; i++) g_focus[i] = (int)w[i];
    else                    for (int i = 0; i < 4; i++) g_focus[i] = p[i] ? 1 : 0;
}

// ---------------------------------------------------------------------------
// tf32 GEMM, 128x128x32 tiles, double-buffered smem, 2-stage pipeline.
// 256 threads = 8 warps (4m x 2n). skip_qk: skip q/k col-blocks of focus rows.
// ---------------------------------------------------------------------------
#define GEMM_SMEM ((2 * 128 * 36 + 2 * 32 * 136) * 4)

__global__ void __launch_bounds__(256, 2) gemm_tf32_db(
    int M, int N, int K,
    const float* __restrict__ A, const float* __restrict__ B, float* __restrict__ C,
    int skip_qk)
{
    extern __shared__ float sm[];
    float* As0 = sm;                 // 2 x (128*36)
    float* Bs0 = sm + 2 * 128 * 36;  // 2 x (32*136)

    const int tid  = threadIdx.x;
    const int lane = tid & 31;
    const int w    = tid >> 5;
    const int wm   = (w >> 1) * 32;
    const int wn   = (w & 1) * 64;
    const int brow = blockIdx.y * 128;
    const int bcol = blockIdx.x * 128;

    if (skip_qk && (bcol + 128 <= 2 * HIDn) && g_focus[brow >> 11]) return;

    float4 ra[4], rb[4];

    float acc[2][8][4];
#pragma unroll
    for (int mt = 0; mt < 2; mt++)
#pragma unroll
        for (int nt = 0; nt < 8; nt++)
#pragma unroll
            for (int i = 0; i < 4; i++) acc[mt][nt][i] = 0.f;

    const int nk = K / 32;

    // prologue: tile 0
#pragma unroll
    for (int it = 0; it < 4; it++) {
        int lin = tid + it * 256;
        int r = lin >> 3, c4 = (lin & 7) * 4;
        ra[it] = *(const float4*)(A + (size_t)(brow + r) * K + c4);
        int rr = lin >> 5, cc = (lin & 31) * 4;
        rb[it] = *(const float4*)(B + (size_t)rr * N + bcol + cc);
    }
#pragma unroll
    for (int it = 0; it < 4; it++) {
        int lin = tid + it * 256;
        int r = lin >> 3, c4 = (lin & 7) * 4;
        *(float4*)(As0 + r * 36 + c4) =
            make_float4(f2tf(ra[it].x), f2tf(ra[it].y), f2tf(ra[it].z), f2tf(ra[it].w));
        int rr = lin >> 5, cc = (lin & 31) * 4;
        *(float4*)(Bs0 + rr * 136 + cc) =
            make_float4(f2tf(rb[it].x), f2tf(rb[it].y), f2tf(rb[it].z), f2tf(rb[it].w));
    }
    __syncthreads();

    for (int kt = 0; kt < nk; kt++) {
        const int p = kt & 1;
        const int k0n = (kt + 1) * 32;

        if (kt + 1 < nk) {
#pragma unroll
            for (int it = 0; it < 4; it++) {
                int lin = tid + it * 256;
                int r = lin >> 3, c4 = (lin & 7) * 4;
                ra[it] = *(const float4*)(A + (size_t)(brow + r) * K + k0n + c4);
                int rr = lin >> 5, cc = (lin & 31) * 4;
                rb[it] = *(const float4*)(B + (size_t)(k0n + rr) * N + bcol + cc);
            }
        }

        const float* Asb = As0 + p * (128 * 36);
        const float* Bsb = Bs0 + p * (32 * 136);
#pragma unroll
        for (int kc = 0; kc < 4; kc++) {
            uint32_t af[2][4];
            const int c = kc * 8 + (lane & 3);
#pragma unroll
            for (int mt = 0; mt < 2; mt++) {
                int row = wm + mt * 16 + (lane >> 2);
                af[mt][0] = __float_as_uint(Asb[row * 36 + c]);
                af[mt][1] = __float_as_uint(Asb[(row + 8) * 36 + c]);
                af[mt][2] = __float_as_uint(Asb[row * 36 + c + 4]);
                af[mt][3] = __float_as_uint(Asb[(row + 8) * 36 + c + 4]);
            }
            const int kr = kc * 8 + (lane & 3);
#pragma unroll
            for (int nt = 0; nt < 8; nt++) {
                int col = wn + nt * 8 + (lane >> 2);
                uint32_t b0 = __float_as_uint(Bsb[kr * 136 + col]);
                uint32_t b1 = __float_as_uint(Bsb[(kr + 4) * 136 + col]);
                mma8(acc[0][nt], af[0], b0, b1);
                mma8(acc[1][nt], af[1], b0, b1);
            }
        }

        if (kt + 1 < nk) {
            float* Asn = As0 + (p ^ 1) * (128 * 36);
            float* Bsn = Bs0 + (p ^ 1) * (32 * 136);
#pragma unroll
            for (int it = 0; it < 4; it++) {
                int lin = tid + it * 256;
                int r = lin >> 3, c4 = (lin & 7) * 4;
                *(float4*)(Asn + r * 36 + c4) =
                    make_float4(f2tf(ra[it].x), f2tf(ra[it].y), f2tf(ra[it].z), f2tf(ra[it].w));
                int rr = lin >> 5, cc = (lin & 31) * 4;
                *(float4*)(Bsn + rr * 136 + cc) =
                    make_float4(f2tf(rb[it].x), f2tf(rb[it].y), f2tf(rb[it].z), f2tf(rb[it].w));
            }
        }
        __syncthreads();
    }

#pragma unroll
    for (int mt = 0; mt < 2; mt++) {
#pragma unroll
        for (int nt = 0; nt < 8; nt++) {
            int r = brow + wm + mt * 16 + (lane >> 2);
            int c = bcol + wn + nt * 8 + (lane & 3) * 2;
            *(float2*)(C + (size_t)r * N + c)       = make_float2(acc[mt][nt][0], acc[mt][nt][1]);
            *(float2*)(C + (size_t)(r + 8) * N + c) = make_float2(acc[mt][nt][2], acc[mt][nt][3]);
        }
    }
}

// ---------------------------------------------------------------------------
// Flash attention, tf32 mma, double-buffered K/V, base-2 softmax.
// Block = 64 q rows of (b,h), 128 threads / 4 warps, warp owns 16 rows.
// ---------------------------------------------------------------------------
#define FLASH_SMEM ((64 * 68 + 2 * 64 * 68 + 2 * 64 * 72 + 64 * 68) * 4)

__global__ void __launch_bounds__(128) flash_tf32_kernel(
    const float* __restrict__ qkv, const float* __restrict__ pos_bias, float* __restrict__ O)
{
    const int qt = blockIdx.x, h = blockIdx.y, b = blockIdx.z;
    const int tid = threadIdx.x, lane = tid & 31, w = tid >> 5;
    const int q0 = qt * 64;

    if (g_focus[b]) {
#pragma unroll
        for (int it = 0; it < 8; it++) {
            int lin = tid + it * 128;
            int r = lin >> 4, c4 = (lin & 15) * 4;
            const float4 v = *(const float4*)(qkv + (size_t)(b * Nn + q0 + r) * (3 * HIDn)
                                              + 2 * HIDn + h * DHn + c4);
            *(float4*)(O + (size_t)(b * Nn + q0 + r) * HIDn + h * DHn + c4) = v;
        }
        return;
    }

    extern __shared__ float sm[];
    float* Qs  = sm;                   // 64 x 68
    float* Ks0 = sm + 64 * 68;         // 2 x (64 x 68)
    float* Vs0 = Ks0 + 2 * 64 * 68;    // 2 x (64 x 72)
    float* Ps  = Vs0 + 2 * 64 * 72;    // 64 x 68

    const float L2E = 1.4426950408889634f;
    const float qscale = 0.125f * L2E;

    float4 kreg[8], vreg[8];

    // prologue: Q (scaled by scale*log2e) + K/V tile 0
#pragma unroll
    for (int it = 0; it < 8; it++) {
        int lin = tid + it * 128;
        int r = lin >> 4, c4 = (lin & 15) * 4;
        const float* base = qkv + (size_t)(b * Nn + q0 + r) * (3 * HIDn) + h * DHn + c4;
        float4 q4 = *(const float4*)(base);
        *(float4*)(Qs + r * 68 + c4) = make_float4(f2tf(q4.x * qscale), f2tf(q4.y * qscale),
                                                   f2tf(q4.z * qscale), f2tf(q4.w * qscale));
        const float* kb = qkv + (size_t)(b * Nn + r) * (3 * HIDn) + h * DHn + c4;
        kreg[it] = *(const float4*)(kb + HIDn);
        vreg[it] = *(const float4*)(kb + 2 * HIDn);
    }
#pragma unroll
    for (int it = 0; it < 8; it++) {
        int lin = tid + it * 128;
        int r = lin >> 4, c4 = (lin & 15) * 4;
        *(float4*)(Ks0 + r * 68 + c4) = make_float4(f2tf(kreg[it].x), f2tf(kreg[it].y),
                                                    f2tf(kreg[it].z), f2tf(kreg[it].w));
        *(float4*)(Vs0 + r * 72 + c4) = make_float4(f2tf(vreg[it].x), f2tf(vreg[it].y),
                                                    f2tf(vreg[it].z), f2tf(vreg[it].w));
    }
    __syncthreads();

    // Q fragments in registers
    uint32_t aq[8][4];
    {
        const int r0 = w * 16 + (lane >> 2);
#pragma unroll
        for (int kc = 0; kc < 8; kc++) {
            int c = kc * 8 + (lane & 3);
            aq[kc][0] = __float_as_uint(Qs[r0 * 68 + c]);
            aq[kc][1] = __float_as_uint(Qs[(r0 + 8) * 68 + c]);
            aq[kc][2] = __float_as_uint(Qs[r0 * 68 + c + 4]);
            aq[kc][3] = __float_as_uint(Qs[(r0 + 8) * 68 + c + 4]);
        }
    }

    float o[8][4];
#pragma unroll
    for (int nt = 0; nt < 8; nt++)
#pragma unroll
        for (int i = 0; i < 4; i++) o[nt][i] = 0.f;
    float m0 = -1e30f, m1 = -1e30f, l0 = 0.f, l1 = 0.f;

    const float* pbbase = pos_bias + ((size_t)h * Nn + (q0 + w * 16 + (lane >> 2))) * Nn
                          + 2 * (lane & 3);

    for (int kt = 0; kt < Nn / 64; kt++) {
        const int p  = kt & 1;
        const int k0 = kt * 64;

        // prefetch next K/V tile
        if (kt + 1 < Nn / 64) {
            const int kn = k0 + 64;
#pragma unroll
            for (int it = 0; it < 8; it++) {
                int lin = tid + it * 128;
                int r = lin >> 4, c4 = (lin & 15) * 4;
                const float* base = qkv + (size_t)(b * Nn + kn + r) * (3 * HIDn) + h * DHn + c4;
                kreg[it] = *(const float4*)(base + HIDn);
                vreg[it] = *(const float4*)(base + 2 * HIDn);
            }
        }

        const float* Ksb = Ks0 + p * (64 * 68);
        const float* Vsb = Vs0 + p * (64 * 72);

        // S = Q @ K^T  (already in log2e units)
        float s[8][4];
#pragma unroll
        for (int nt = 0; nt < 8; nt++)
#pragma unroll
            for (int i = 0; i < 4; i++) s[nt][i] = 0.f;
#pragma unroll
        for (int kc = 0; kc < 8; kc++) {
            const int d = kc * 8 + (lane & 3);
#pragma unroll
            for (int nt = 0; nt < 8; nt++) {
                int kr = nt * 8 + (lane >> 2);
                uint32_t b0 = __float_as_uint(Ksb[kr * 68 + d]);
                uint32_t b1 = __float_as_uint(Ksb[kr * 68 + d + 4]);
                mma8(s[nt], aq[kc], b0, b1);
            }
        }

        // + pos_bias * log2e
        const float* pb0 = pbbase + k0;
        const float* pb1 = pb0 + 8 * Nn;
#pragma unroll
        for (int nt = 0; nt < 8; nt++) {
            float2 x0 = *(const float2*)(pb0 + nt * 8);
            float2 x1 = *(const float2*)(pb1 + nt * 8);
            s[nt][0] = fmaf(x0.x, L2E, s[nt][0]);
            s[nt][1] = fmaf(x0.y, L2E, s[nt][1]);
            s[nt][2] = fmaf(x1.x, L2E, s[nt][2]);
            s[nt][3] = fmaf(x1.y, L2E, s[nt][3]);
        }

        // Online softmax (base 2)
        float rmax0 = -1e30f, rmax1 = -1e30f;
#pragma unroll
        for (int nt = 0; nt < 8; nt++) {
            rmax0 = fmaxf(rmax0, fmaxf(s[nt][0], s[nt][1]));
            rmax1 = fmaxf(rmax1, fmaxf(s[nt][2], s[nt][3]));
        }
#pragma unroll
        for (int off = 1; off <= 2; off <<= 1) {
            rmax0 = fmaxf(rmax0, __shfl_xor_sync(0xffffffffu, rmax0, off));
            rmax1 = fmaxf(rmax1, __shfl_xor_sync(0xffffffffu, rmax1, off));
        }
        float mn0 = fmaxf(m0, rmax0), mn1 = fmaxf(m1, rmax1);
        float corr0 = ex2f(m0 - mn0), corr1 = ex2f(m1 - mn1);
        float rs0 = 0.f, rs1 = 0.f;
#pragma unroll
        for (int nt = 0; nt < 8; nt++) {
            s[nt][0] = ex2f(s[nt][0] - mn0); rs0 += s[nt][0];
            s[nt][1] = ex2f(s[nt][1] - mn0); rs0 += s[nt][1];
            s[nt][2] = ex2f(s[nt][2] - mn1); rs1 += s[nt][2];
            s[nt][3] = ex2f(s[nt][3] - mn1); rs1 += s[nt][3];
        }
#pragma unroll
        for (int off = 1; off <= 2; off <<= 1) {
            rs0 += __shfl_xor_sync(0xffffffffu, rs0, off);
            rs1 += __shfl_xor_sync(0xffffffffu, rs1, off);
        }
        l0 = l0 * corr0 + rs0;  m0 = mn0;
        l1 = l1 * corr1 + rs1;  m1 = mn1;
#pragma unroll
        for (int nt = 0; nt < 8; nt++) {
            o[nt][0] *= corr0; o[nt][1] *= corr0;
            o[nt][2] *= corr1; o[nt][3] *= corr1;
        }

        // P -> smem (tf32), warp-local rows, float2 stores
        {
            int pr = w * 16 + (lane >> 2);
            int pc = 2 * (lane & 3);
#pragma unroll
            for (int nt = 0; nt < 8; nt++) {
                *(float2*)(Ps + pr * 68 + nt * 8 + pc) =
                    make_float2(f2tf(s[nt][0]), f2tf(s[nt][1]));
                *(float2*)(Ps + (pr + 8) * 68 + nt * 8 + pc) =
                    make_float2(f2tf(s[nt][2]), f2tf(s[nt][3]));
            }
        }
        __syncwarp();

        // O += P @ V
#pragma unroll
        for (int kc = 0; kc < 8; kc++) {
            uint32_t pa[4];
            int pr = w * 16 + (lane >> 2);
            int pcc = kc * 8 + (lane & 3);
            pa[0] = __float_as_uint(Ps[pr * 68 + pcc]);
            pa[1] = __float_as_uint(Ps[(pr + 8) * 68 + pcc]);
            pa[2] = __float_as_uint(Ps[pr * 68 + pcc + 4]);
            pa[3] = __float_as_uint(Ps[(pr + 8) * 68 + pcc + 4]);
            const int vr = kc * 8 + (lane & 3);
#pragma unroll
            for (int nt = 0; nt < 8; nt++) {
                int vc = nt * 8 + (lane >> 2);
                uint32_t b0 = __float_as_uint(Vsb[vr * 72 + vc]);
                uint32_t b1 = __float_as_uint(Vsb[(vr + 4) * 72 + vc]);
                mma8(o[nt], pa, b0, b1);
            }
        }

        // store prefetched tile into other buffer
        if (kt + 1 < Nn / 64) {
            float* Ksn = Ks0 + (p ^ 1) * (64 * 68);
            float* Vsn = Vs0 + (p ^ 1) * (64 * 72);
#pragma unroll
            for (int it = 0; it < 8; it++) {
                int lin = tid + it * 128;
                int r = lin >> 4, c4 = (lin & 15) * 4;
                *(float4*)(Ksn + r * 68 + c4) = make_float4(f2tf(kreg[it].x), f2tf(kreg[it].y),
                                                            f2tf(kreg[it].z), f2tf(kreg[it].w));
                *(float4*)(Vsn + r * 72 + c4) = make_float4(f2tf(vreg[it].x), f2tf(vreg[it].y),
                                                            f2tf(vreg[it].z), f2tf(vreg[it].w));
            }
        }
        __syncthreads();
    }

    // Normalize + store
    float inv0 = 1.f / l0, inv1 = 1.f / l1;
    int gr = b * Nn + q0 + w * 16 + (lane >> 2);
    float* op = O + (size_t)gr * HIDn + h * DHn + 2 * (lane & 3);
#pragma unroll
    for (int nt = 0; nt < 8; nt++) {
        *(float2*)(op + nt * 8)            = make_float2(o[nt][0] * inv0, o[nt][1] * inv0);
        *(float2*)(op + 8 * HIDn + nt * 8) = make_float2(o[nt][2] * inv1, o[nt][3] * inv1);
    }
}

// ---------------------------------------------------------------------------
extern "C" void kernel_launch(void* const* d_in, const int* in_sizes, int n_in,
                              void* d_out, int out_size)
{
    const float*         x        = (const float*)d_in[0];
    const float*         pos_bias = (const float*)d_in[1];
    const unsigned char* maskp    = (const unsigned char*)d_in[2];
    const float*         w_qkv    = (const float*)d_in[3];
    const float*         w_out    = (const float*)d_in[4];
    float*               out      = (float*)d_out;

    float *qkv_ptr, *o_ptr;
    cudaGetSymbolAddress((void**)&qkv_ptr, g_qkv);
    cudaGetSymbolAddress((void**)&o_ptr,   g_o);

    cudaFuncSetAttribute(gemm_tf32_db, cudaFuncAttributeMaxDynamicSharedMemorySize, GEMM_SMEM);
    cudaFuncSetAttribute(flash_tf32_kernel, cudaFuncAttributeMaxDynamicSharedMemorySize, FLASH_SMEM);

    decode_mask_kernel<<<1, 1>>>(maskp);

    // qkv = x @ w_qkv (q/k col-blocks skipped for focus batches)
    gemm_tf32_db<<<dim3(1536 / 128, 8192 / 128), 256, GEMM_SMEM>>>(
        8192, 1536, 512, x, w_qkv, qkv_ptr, 1);

    // fused flash attention
    flash_tf32_kernel<<<dim3(Nn / 64, HEADSn, Bn), 128, FLASH_SMEM>>>(qkv_ptr, pos_bias, o_ptr);

    // out = O @ w_out
    gemm_tf32_db<<<dim3(512 / 128, 8192 / 128), 256, GEMM_SMEM>>>(
        8192, 512, 512, o_ptr, w_out, out, 0);
}

// round 4
// speedup vs baseline: 3.9601x; 1.4682x over previous
#include <cuda_runtime.h>
#include <cuda_fp16.h>
#include <math.h>
#include <stdint.h>

#define Bn    4
#define Nn    2048
#define DIMn  512
#define HEADSn 8
#define DHn   64
#define HIDn  512

__device__ float g_qkv[Bn * Nn * 3 * HIDn];   // (B,N,1536): q|k|v
__device__ float g_o  [Bn * Nn * HIDn];       // (B,N,512)
__device__ int   g_focus[Bn];

// ---------------------------------------------------------------------------
__device__ __forceinline__ float ex2f(float x) {
    float r;
    asm("ex2.approx.ftz.f32 %0, %1;" : "=f"(r) : "f"(x));
    return r;
}
__device__ __forceinline__ uint32_t pack2(float a, float b) {
    __half2 h = __floats2half2_rn(a, b);   // lo = a, hi = b
    return *reinterpret_cast<uint32_t*>(&h);
}
// D += A(16x16,row) * B(16x8,col), fp16 in, fp32 accum
__device__ __forceinline__ void mma16(float* d, const uint32_t* a, uint32_t b0, uint32_t b1) {
    asm volatile(
        "mma.sync.aligned.m16n8k16.row.col.f32.f16.f16.f32 "
        "{%0,%1,%2,%3}, {%4,%5,%6,%7}, {%8,%9}, {%0,%1,%2,%3};"
        : "+f"(d[0]), "+f"(d[1]), "+f"(d[2]), "+f"(d[3])
        : "r"(a[0]), "r"(a[1]), "r"(a[2]), "r"(a[3]), "r"(b0), "r"(b1));
}

// ---------------------------------------------------------------------------
__global__ void decode_mask_kernel(const unsigned char* __restrict__ p) {
    unsigned int w[4];
#pragma unroll
    for (int i = 0; i < 4; i++) w[i] = ((const unsigned int*)p)[i];
    bool allF = true, allI = true, anyNZ = false;
#pragma unroll
    for (int i = 0; i < 4; i++) {
        if (w[i] != 0u) anyNZ = true;
        if (w[i] != 0u && w[i] != 0x3F800000u) allF = false;
        if (w[i] > 1u) allI = false;
    }
    if (anyNZ && allF)      for (int i = 0; i < 4; i++) g_focus[i] = (w[i] == 0x3F800000u);
    else if (allI)          for (int i = 0; i < 4; i++) g_focus[i] = (int)w[i];
    else                    for (int i = 0; i < 4; i++) g_focus[i] = p[i] ? 1 : 0;
}

// ---------------------------------------------------------------------------
// fp16 GEMM, 128x128x32 tiles, double-buffered, 2-stage pipeline.
// A fp32 [M][K] row-major -> As halves [m][k] stride 40.
// B fp32 [K][N] row-major -> Bst halves [n][k] stride 40 (transposed at store).
// ---------------------------------------------------------------------------
#define GS 40
#define GBUF (128 * GS)
#define GEMM_SMEM (4 * GBUF * 2)   // 2xA + 2xB buffers, halves

__global__ void __launch_bounds__(256, 2) gemm_h16(
    int M, int N, int K,
    const float* __restrict__ A, const float* __restrict__ B, float* __restrict__ C,
    int skip_qk)
{
    extern __shared__ __half smh[];
    __half* AsB = smh;              // 2 x GBUF
    __half* BsB = smh + 2 * GBUF;   // 2 x GBUF

    const int tid  = threadIdx.x;
    const int lane = tid & 31;
    const int w    = tid >> 5;
    const int wm   = (w >> 1) * 32;
    const int wn   = (w & 1) * 64;
    const int brow = blockIdx.y * 128;
    const int bcol = blockIdx.x * 128;

    if (skip_qk && (bcol + 128 <= 2 * HIDn) && g_focus[brow >> 11]) return;

    float4 ra[4];
    float  rb[4][4];

    float acc[2][8][4];
#pragma unroll
    for (int mt = 0; mt < 2; mt++)
#pragma unroll
        for (int nt = 0; nt < 8; nt++)
#pragma unroll
            for (int i = 0; i < 4; i++) acc[mt][nt][i] = 0.f;

    const int nk = K / 32;

    // ---- prologue: tile 0 ----
#pragma unroll
    for (int it = 0; it < 4; it++) {
        int lin = tid + it * 256;
        int r = lin >> 3, c4 = (lin & 7) * 4;
        ra[it] = *(const float4*)(A + (size_t)(brow + r) * K + c4);
        int n = lin & 127, k0b = (lin >> 7) * 4;
#pragma unroll
        for (int j = 0; j < 4; j++)
            rb[it][j] = B[(size_t)(k0b + j) * N + bcol + n];
    }
#pragma unroll
    for (int it = 0; it < 4; it++) {
        int lin = tid + it * 256;
        int r = lin >> 3, c4 = (lin & 7) * 4;
        uint2 pa = make_uint2(pack2(ra[it].x, ra[it].y), pack2(ra[it].z, ra[it].w));
        *(uint2*)(AsB + r * GS + c4) = pa;
        int n = lin & 127, k0b = (lin >> 7) * 4;
        uint2 pb = make_uint2(pack2(rb[it][0], rb[it][1]), pack2(rb[it][2], rb[it][3]));
        *(uint2*)(BsB + n * GS + k0b) = pb;
    }
    __syncthreads();

    for (int kt = 0; kt < nk; kt++) {
        const int p   = kt & 1;
        const int k0n = (kt + 1) * 32;

        if (kt + 1 < nk) {
#pragma unroll
            for (int it = 0; it < 4; it++) {
                int lin = tid + it * 256;
                int r = lin >> 3, c4 = (lin & 7) * 4;
                ra[it] = *(const float4*)(A + (size_t)(brow + r) * K + k0n + c4);
                int n = lin & 127, k0b = (lin >> 7) * 4;
#pragma unroll
                for (int j = 0; j < 4; j++)
                    rb[it][j] = B[(size_t)(k0n + k0b + j) * N + bcol + n];
            }
        }

        const __half* Asb = AsB + p * GBUF;
        const __half* Bsb = BsB + p * GBUF;
#pragma unroll
        for (int kc = 0; kc < 2; kc++) {
            const int c = kc * 16 + (lane & 3) * 2;
            uint32_t af[2][4];
#pragma unroll
            for (int mt = 0; mt < 2; mt++) {
                int row = wm + mt * 16 + (lane >> 2);
                af[mt][0] = *(const uint32_t*)(Asb + row * GS + c);
                af[mt][1] = *(const uint32_t*)(Asb + (row + 8) * GS + c);
                af[mt][2] = *(const uint32_t*)(Asb + row * GS + c + 8);
                af[mt][3] = *(const uint32_t*)(Asb + (row + 8) * GS + c + 8);
            }
#pragma unroll
            for (int nt = 0; nt < 8; nt++) {
                int col = wn + nt * 8 + (lane >> 2);
                uint32_t b0 = *(const uint32_t*)(Bsb + col * GS + c);
                uint32_t b1 = *(const uint32_t*)(Bsb + col * GS + c + 8);
                mma16(acc[0][nt], af[0], b0, b1);
                mma16(acc[1][nt], af[1], b0, b1);
            }
        }

        if (kt + 1 < nk) {
            __half* Asn = AsB + (p ^ 1) * GBUF;
            __half* Bsn = BsB + (p ^ 1) * GBUF;
#pragma unroll
            for (int it = 0; it < 4; it++) {
                int lin = tid + it * 256;
                int r = lin >> 3, c4 = (lin & 7) * 4;
                *(uint2*)(Asn + r * GS + c4) =
                    make_uint2(pack2(ra[it].x, ra[it].y), pack2(ra[it].z, ra[it].w));
                int n = lin & 127, k0b = (lin >> 7) * 4;
                *(uint2*)(Bsn + n * GS + k0b) =
                    make_uint2(pack2(rb[it][0], rb[it][1]), pack2(rb[it][2], rb[it][3]));
            }
        }
        __syncthreads();
    }

#pragma unroll
    for (int mt = 0; mt < 2; mt++) {
#pragma unroll
        for (int nt = 0; nt < 8; nt++) {
            int r = brow + wm + mt * 16 + (lane >> 2);
            int c = bcol + wn + nt * 8 + (lane & 3) * 2;
            *(float2*)(C + (size_t)r * N + c)       = make_float2(acc[mt][nt][0], acc[mt][nt][1]);
            *(float2*)(C + (size_t)(r + 8) * N + c) = make_float2(acc[mt][nt][2], acc[mt][nt][3]);
        }
    }
}

// ---------------------------------------------------------------------------
// Flash attention, fp16 mma m16n8k16, P kept in registers, double-buffered K/Vt.
// Block = 64 q rows of (b,h), 128 threads / 4 warps (16 rows/warp).
// Ks: [key][d] halves stride 72. Vt: [d][key] halves stride 72 (transposed).
// ---------------------------------------------------------------------------
#define FS 72
#define FBUF (64 * FS)
#define FLASH_SMEM (5 * FBUF * 2)   // Qs + 2xKs + 2xVt, halves

__global__ void __launch_bounds__(128) flash_h16(
    const float* __restrict__ qkv, const float* __restrict__ pos_bias, float* __restrict__ O)
{
    const int qt = blockIdx.x, h = blockIdx.y, b = blockIdx.z;
    const int tid = threadIdx.x, lane = tid & 31, w = tid >> 5;
    const int q0 = qt * 64;

    if (g_focus[b]) {
#pragma unroll
        for (int it = 0; it < 8; it++) {
            int lin = tid + it * 128;
            int r = lin >> 4, c4 = (lin & 15) * 4;
            const float4 v = *(const float4*)(qkv + (size_t)(b * Nn + q0 + r) * (3 * HIDn)
                                              + 2 * HIDn + h * DHn + c4);
            *(float4*)(O + (size_t)(b * Nn + q0 + r) * HIDn + h * DHn + c4) = v;
        }
        return;
    }

    extern __shared__ __half smh[];
    __half* Qs  = smh;               // 64 x 72
    __half* KsB = smh + FBUF;        // 2 x (64 x 72)   [key][d]
    __half* VtB = smh + 3 * FBUF;    // 2 x (64 x 72)   [d][key]

    const float L2E = 1.4426950408889634f;
    const float qscale = 0.125f * L2E;

    float4 kreg[8];
    float  vreg[8][4];

    // ---- prologue: Q (scaled), K tile0, V tile0 ----
#pragma unroll
    for (int it = 0; it < 8; it++) {
        int lin = tid + it * 128;
        int r = lin >> 4, c4 = (lin & 15) * 4;
        const float* base = qkv + (size_t)(b * Nn + q0 + r) * (3 * HIDn) + h * DHn + c4;
        float4 q4 = *(const float4*)(base);
        *(uint2*)(Qs + r * FS + c4) = make_uint2(pack2(q4.x * qscale, q4.y * qscale),
                                                 pack2(q4.z * qscale, q4.w * qscale));
        const float* kb = qkv + (size_t)(b * Nn + r) * (3 * HIDn) + HIDn + h * DHn + c4;
        float4 k4 = *(const float4*)(kb);
        *(uint2*)(KsB + r * FS + c4) = make_uint2(pack2(k4.x, k4.y), pack2(k4.z, k4.w));
        // V transposed: d = lin & 63, keys k0..k0+3
        int d = lin & 63, k0v = (lin >> 6) * 4;
        const float* vb = qkv + (size_t)(b * Nn + k0v) * (3 * HIDn) + 2 * HIDn + h * DHn + d;
        float v0 = vb[0], v1 = vb[3 * HIDn], v2 = vb[6 * HIDn], v3 = vb[9 * HIDn];
        *(uint2*)(VtB + d * FS + k0v) = make_uint2(pack2(v0, v1), pack2(v2, v3));
    }
    __syncthreads();

    // Q fragments in registers (A operand, 4 k-chunks of 16)
    uint32_t aq[4][4];
    {
        const int r0 = w * 16 + (lane >> 2);
#pragma unroll
        for (int kc = 0; kc < 4; kc++) {
            int c = kc * 16 + (lane & 3) * 2;
            aq[kc][0] = *(const uint32_t*)(Qs + r0 * FS + c);
            aq[kc][1] = *(const uint32_t*)(Qs + (r0 + 8) * FS + c);
            aq[kc][2] = *(const uint32_t*)(Qs + r0 * FS + c + 8);
            aq[kc][3] = *(const uint32_t*)(Qs + (r0 + 8) * FS + c + 8);
        }
    }

    float o[8][4];
#pragma unroll
    for (int nt = 0; nt < 8; nt++)
#pragma unroll
        for (int i = 0; i < 4; i++) o[nt][i] = 0.f;
    float m0 = -1e30f, m1 = -1e30f, l0 = 0.f, l1 = 0.f;

    const float* pbbase = pos_bias + ((size_t)h * Nn + (q0 + w * 16 + (lane >> 2))) * Nn
                          + 2 * (lane & 3);

    for (int kt = 0; kt < Nn / 64; kt++) {
        const int p  = kt & 1;
        const int k0 = kt * 64;
        const bool more = (kt + 1 < Nn / 64);

        // (A) issue next K loads
        if (more) {
            const int kn = k0 + 64;
#pragma unroll
            for (int it = 0; it < 8; it++) {
                int lin = tid + it * 128;
                int r = lin >> 4, c4 = (lin & 15) * 4;
                kreg[it] = *(const float4*)(qkv + (size_t)(b * Nn + kn + r) * (3 * HIDn)
                                            + HIDn + h * DHn + c4);
            }
        }

        const __half* Ksb = KsB + p * FBUF;
        const __half* Vtb = VtB + p * FBUF;

        // (B) S = Q @ K^T  (log2e folded into Q)
        float s[8][4];
#pragma unroll
        for (int nt = 0; nt < 8; nt++)
#pragma unroll
            for (int i = 0; i < 4; i++) s[nt][i] = 0.f;
#pragma unroll
        for (int kc = 0; kc < 4; kc++) {
            const int c = kc * 16 + (lane & 3) * 2;
#pragma unroll
            for (int nt = 0; nt < 8; nt++) {
                int kr = nt * 8 + (lane >> 2);
                uint32_t b0 = *(const uint32_t*)(Ksb + kr * FS + c);
                uint32_t b1 = *(const uint32_t*)(Ksb + kr * FS + c + 8);
                mma16(s[nt], aq[kc], b0, b1);
            }
        }

        // (C) + pos_bias * log2e, online softmax (base 2)
        const float* pb0 = pbbase + k0;
        const float* pb1 = pb0 + 8 * Nn;
#pragma unroll
        for (int nt = 0; nt < 8; nt++) {
            float2 x0 = *(const float2*)(pb0 + nt * 8);
            float2 x1 = *(const float2*)(pb1 + nt * 8);
            s[nt][0] = fmaf(x0.x, L2E, s[nt][0]);
            s[nt][1] = fmaf(x0.y, L2E, s[nt][1]);
            s[nt][2] = fmaf(x1.x, L2E, s[nt][2]);
            s[nt][3] = fmaf(x1.y, L2E, s[nt][3]);
        }

        float rmax0 = -1e30f, rmax1 = -1e30f;
#pragma unroll
        for (int nt = 0; nt < 8; nt++) {
            rmax0 = fmaxf(rmax0, fmaxf(s[nt][0], s[nt][1]));
            rmax1 = fmaxf(rmax1, fmaxf(s[nt][2], s[nt][3]));
        }
#pragma unroll
        for (int off = 1; off <= 2; off <<= 1) {
            rmax0 = fmaxf(rmax0, __shfl_xor_sync(0xffffffffu, rmax0, off));
            rmax1 = fmaxf(rmax1, __shfl_xor_sync(0xffffffffu, rmax1, off));
        }
        float mn0 = fmaxf(m0, rmax0), mn1 = fmaxf(m1, rmax1);
        float corr0 = ex2f(m0 - mn0), corr1 = ex2f(m1 - mn1);
        float rs0 = 0.f, rs1 = 0.f;
#pragma unroll
        for (int nt = 0; nt < 8; nt++) {
            s[nt][0] = ex2f(s[nt][0] - mn0); rs0 += s[nt][0];
            s[nt][1] = ex2f(s[nt][1] - mn0); rs0 += s[nt][1];
            s[nt][2] = ex2f(s[nt][2] - mn1); rs1 += s[nt][2];
            s[nt][3] = ex2f(s[nt][3] - mn1); rs1 += s[nt][3];
        }
#pragma unroll
        for (int off = 1; off <= 2; off <<= 1) {
            rs0 += __shfl_xor_sync(0xffffffffu, rs0, off);
            rs1 += __shfl_xor_sync(0xffffffffu, rs1, off);
        }
        l0 = l0 * corr0 + rs0;  m0 = mn0;
        l1 = l1 * corr1 + rs1;  m1 = mn1;
#pragma unroll
        for (int nt = 0; nt < 8; nt++) {
            o[nt][0] *= corr0; o[nt][1] *= corr0;
            o[nt][2] *= corr1; o[nt][3] *= corr1;
        }

        // (D) store next K tile into other buffer
        if (more) {
            __half* Ksn = KsB + (p ^ 1) * FBUF;
#pragma unroll
            for (int it = 0; it < 8; it++) {
                int lin = tid + it * 128;
                int r = lin >> 4, c4 = (lin & 15) * 4;
                *(uint2*)(Ksn + r * FS + c4) = make_uint2(pack2(kreg[it].x, kreg[it].y),
                                                          pack2(kreg[it].z, kreg[it].w));
            }
        }

        // (E) P fragments straight from S registers (accumulator layout == A layout)
        uint32_t pa[4][4];
#pragma unroll
        for (int kc = 0; kc < 4; kc++) {
            pa[kc][0] = pack2(s[2 * kc][0],     s[2 * kc][1]);
            pa[kc][1] = pack2(s[2 * kc][2],     s[2 * kc][3]);
            pa[kc][2] = pack2(s[2 * kc + 1][0], s[2 * kc + 1][1]);
            pa[kc][3] = pack2(s[2 * kc + 1][2], s[2 * kc + 1][3]);
        }

        // (F) issue next V loads (transposed gather: 4 keys per thread, fixed d)
        if (more) {
            const int kn = k0 + 64;
#pragma unroll
            for (int it = 0; it < 8; it++) {
                int lin = tid + it * 128;
                int d = lin & 63, k0v = (lin >> 6) * 4;
                const float* vb = qkv + (size_t)(b * Nn + kn + k0v) * (3 * HIDn)
                                  + 2 * HIDn + h * DHn + d;
                vreg[it][0] = vb[0];
                vreg[it][1] = vb[3 * HIDn];
                vreg[it][2] = vb[6 * HIDn];
                vreg[it][3] = vb[9 * HIDn];
            }
        }

        // (G) O += P @ V   (B operand from Vt, pairs over keys contiguous)
#pragma unroll
        for (int kc = 0; kc < 4; kc++) {
            const int c = kc * 16 + (lane & 3) * 2;
#pragma unroll
            for (int nt = 0; nt < 8; nt++) {
                int vd = nt * 8 + (lane >> 2);
                uint32_t b0 = *(const uint32_t*)(Vtb + vd * FS + c);
                uint32_t b1 = *(const uint32_t*)(Vtb + vd * FS + c + 8);
                mma16(o[nt], pa[kc], b0, b1);
            }
        }

        // (H) store next V tile (transposed)
        if (more) {
            __half* Vtn = VtB + (p ^ 1) * FBUF;
#pragma unroll
            for (int it = 0; it < 8; it++) {
                int lin = tid + it * 128;
                int d = lin & 63, k0v = (lin >> 6) * 4;
                *(uint2*)(Vtn + d * FS + k0v) =
                    make_uint2(pack2(vreg[it][0], vreg[it][1]),
                               pack2(vreg[it][2], vreg[it][3]));
            }
        }
        __syncthreads();
    }

    // Normalize + store
    float inv0 = 1.f / l0, inv1 = 1.f / l1;
    int gr = b * Nn + q0 + w * 16 + (lane >> 2);
    float* op = O + (size_t)gr * HIDn + h * DHn + 2 * (lane & 3);
#pragma unroll
    for (int nt = 0; nt < 8; nt++) {
        *(float2*)(op + nt * 8)            = make_float2(o[nt][0] * inv0, o[nt][1] * inv0);
        *(float2*)(op + 8 * HIDn + nt * 8) = make_float2(o[nt][2] * inv1, o[nt][3] * inv1);
    }
}

// ---------------------------------------------------------------------------
extern "C" void kernel_launch(void* const* d_in, const int* in_sizes, int n_in,
                              void* d_out, int out_size)
{
    const float*         x        = (const float*)d_in[0];
    const float*         pos_bias = (const float*)d_in[1];
    const unsigned char* maskp    = (const unsigned char*)d_in[2];
    const float*         w_qkv    = (const float*)d_in[3];
    const float*         w_out    = (const float*)d_in[4];
    float*               out      = (float*)d_out;

    float *qkv_ptr, *o_ptr;
    cudaGetSymbolAddress((void**)&qkv_ptr, g_qkv);
    cudaGetSymbolAddress((void**)&o_ptr,   g_o);

    cudaFuncSetAttribute(gemm_h16,  cudaFuncAttributeMaxDynamicSharedMemorySize, GEMM_SMEM);
    cudaFuncSetAttribute(flash_h16, cudaFuncAttributeMaxDynamicSharedMemorySize, FLASH_SMEM);

    decode_mask_kernel<<<1, 1>>>(maskp);

    // qkv = x @ w_qkv (q/k col-blocks skipped for focus batches)
    gemm_h16<<<dim3(1536 / 128, 8192 / 128), 256, GEMM_SMEM>>>(
        8192, 1536, 512, x, w_qkv, qkv_ptr, 1);

    // fused flash attention
    flash_h16<<<dim3(Nn / 64, HEADSn, Bn), 128, FLASH_SMEM>>>(qkv_ptr, pos_bias, o_ptr);

    // out = O @ w_out
    gemm_h16<<<dim3(512 / 128, 8192 / 128), 256, GEMM_SMEM>>>(
        8192, 512, 512, o_ptr, w_out, out, 0);
}

// round 5
// speedup vs baseline: 4.0799x; 1.0302x over previous
#include <cuda_runtime.h>
#include <cuda_fp16.h>
#include <stdint.h>

#define Bn    4
#define Nn    2048
#define HEADSn 8
#define DHn   64
#define HIDn  512
#define L2E   1.4426950408889634f
#define QSCALEC (0.125f * 1.4426950408889634f)

// Scratch (device globals; allocation-free rule)
__device__ __half g_xh   [Bn * Nn * 512];
__device__ __half g_wqkvh[512 * 1536];
__device__ __half g_wouth[512 * 512];
__device__ __half g_qkvh [Bn * Nn * 1536];   // q|k|v halves
__device__ __half g_oh   [Bn * Nn * 512];
__device__ int    g_focus[Bn];

// ---------------------------------------------------------------------------
__device__ __forceinline__ float ex2f(float x) {
    float r; asm("ex2.approx.ftz.f32 %0, %1;" : "=f"(r) : "f"(x)); return r;
}
__device__ __forceinline__ uint32_t ex2h2(float a, float b) {
    __half2 h = __floats2half2_rn(a, b);
    uint32_t u = *reinterpret_cast<uint32_t*>(&h);
    asm("ex2.approx.f16x2 %0, %0;" : "+r"(u));
    return u;
}
__device__ __forceinline__ uint32_t packh2(__half a, __half b) {
    __half2 h = __halves2half2(a, b);
    return *reinterpret_cast<uint32_t*>(&h);
}
__device__ __forceinline__ uint32_t packf2(float a, float b) {
    __half2 h = __floats2half2_rn(a, b);
    return *reinterpret_cast<uint32_t*>(&h);
}
__device__ __forceinline__ void mma16(float* d, const uint32_t* a, uint32_t b0, uint32_t b1) {
    asm volatile(
        "mma.sync.aligned.m16n8k16.row.col.f32.f16.f16.f32 "
        "{%0,%1,%2,%3}, {%4,%5,%6,%7}, {%8,%9}, {%0,%1,%2,%3};"
        : "+f"(d[0]), "+f"(d[1]), "+f"(d[2]), "+f"(d[3])
        : "r"(a[0]), "r"(a[1]), "r"(a[2]), "r"(a[3]), "r"(b0), "r"(b1));
}
__device__ __forceinline__ void cpa16(void* s, const void* g) {
    uint32_t sa = (uint32_t)__cvta_generic_to_shared(s);
    asm volatile("cp.async.ca.shared.global [%0], [%1], 16;" :: "r"(sa), "l"(g));
}
__device__ __forceinline__ void cpa8(void* s, const void* g) {
    uint32_t sa = (uint32_t)__cvta_generic_to_shared(s);
    asm volatile("cp.async.ca.shared.global [%0], [%1], 8;" :: "r"(sa), "l"(g));
}
#define CP_COMMIT() asm volatile("cp.async.commit_group;")
#define CP_WAIT0()  asm volatile("cp.async.wait_group 0;")

// ---------------------------------------------------------------------------
__global__ void decode_mask_kernel(const unsigned char* __restrict__ p) {
    unsigned int w[4];
#pragma unroll
    for (int i = 0; i < 4; i++) w[i] = ((const unsigned int*)p)[i];
    bool allF = true, allI = true, anyNZ = false;
#pragma unroll
    for (int i = 0; i < 4; i++) {
        if (w[i] != 0u) anyNZ = true;
        if (w[i] != 0u && w[i] != 0x3F800000u) allF = false;
        if (w[i] > 1u) allI = false;
    }
    if (anyNZ && allF)      for (int i = 0; i < 4; i++) g_focus[i] = (w[i] == 0x3F800000u);
    else if (allI)          for (int i = 0; i < 4; i++) g_focus[i] = (int)w[i];
    else                    for (int i = 0; i < 4; i++) g_focus[i] = p[i] ? 1 : 0;
}

// fp32 -> fp16 bulk convert (n divisible by 4)
__global__ void f2h_kernel(const float4* __restrict__ src, uint2* __restrict__ dst, int n4) {
    int i = blockIdx.x * blockDim.x + threadIdx.x;
    if (i < n4) {
        float4 v = src[i];
        dst[i] = make_uint2(packf2(v.x, v.y), packf2(v.z, v.w));
    }
}

// ---------------------------------------------------------------------------
// half GEMM: C(MxN) = A(MxK) @ B(KxN). A,B half. C half or float.
// 128x128x32 tiles, double-buffered, cp.async for A, 256 thr / 8 warps.
// ---------------------------------------------------------------------------
#define GS 40
#define GBUF (128 * GS)
#define GEMM_SMEM (4 * GBUF * 2)

__global__ void __launch_bounds__(256, 2) gemm_h(
    int M, int N, int K,
    const __half* __restrict__ A, const __half* __restrict__ B, void* __restrict__ Cv,
    int is_qkv, float qmul, int half_out)
{
    extern __shared__ __half smh[];
    __half* AsB = smh;              // 2 x GBUF
    __half* BsB = smh + 2 * GBUF;   // 2 x GBUF

    const int tid  = threadIdx.x;
    const int lane = tid & 31;
    const int w    = tid >> 5;
    const int wm   = (w >> 1) * 32;
    const int wn   = (w & 1) * 64;
    const int brow = blockIdx.y * 128;
    const int bcol = blockIdx.x * 128;

    if (is_qkv && (bcol + 128 <= 1024) && g_focus[brow >> 11]) return;

    uint2 rbp[4];

    float acc[2][8][4];
#pragma unroll
    for (int mt = 0; mt < 2; mt++)
#pragma unroll
        for (int nt = 0; nt < 8; nt++)
#pragma unroll
            for (int i = 0; i < 4; i++) acc[mt][nt][i] = 0.f;

    const int nk = K / 32;

    // ---- prologue: tile 0 ----
#pragma unroll
    for (int it = 0; it < 2; it++) {             // A via cp.async (16B each)
        int lin = tid + it * 256;
        int r = lin >> 2, cs = (lin & 3) * 8;
        cpa16(AsB + r * GS + cs, A + (size_t)(brow + r) * K + cs);
    }
    CP_COMMIT();
#pragma unroll
    for (int it = 0; it < 4; it++) {             // B gather (transpose)
        int lin = tid + it * 256;
        int n = lin & 127, kb = (lin >> 7) * 4;
        const __half* bp = B + (size_t)kb * N + bcol + n;
        rbp[it] = make_uint2(packh2(bp[0], bp[N]), packh2(bp[2 * N], bp[3 * N]));
    }
#pragma unroll
    for (int it = 0; it < 4; it++) {
        int lin = tid + it * 256;
        int n = lin & 127, kb = (lin >> 7) * 4;
        *(uint2*)(BsB + n * GS + kb) = rbp[it];
    }
    CP_WAIT0();
    __syncthreads();

    for (int kt = 0; kt < nk; kt++) {
        const int p   = kt & 1;
        const int k0n = (kt + 1) * 32;
        const bool more = (kt + 1 < nk);

        if (more) {
#pragma unroll
            for (int it = 0; it < 2; it++) {
                int lin = tid + it * 256;
                int r = lin >> 2, cs = (lin & 3) * 8;
                cpa16(AsB + (p ^ 1) * GBUF + r * GS + cs,
                      A + (size_t)(brow + r) * K + k0n + cs);
            }
            CP_COMMIT();
#pragma unroll
            for (int it = 0; it < 4; it++) {
                int lin = tid + it * 256;
                int n = lin & 127, kb = (lin >> 7) * 4;
                const __half* bp = B + (size_t)(k0n + kb) * N + bcol + n;
                rbp[it] = make_uint2(packh2(bp[0], bp[N]), packh2(bp[2 * N], bp[3 * N]));
            }
        }

        const __half* Asb = AsB + p * GBUF;
        const __half* Bsb = BsB + p * GBUF;
#pragma unroll
        for (int kc = 0; kc < 2; kc++) {
            const int c = kc * 16 + (lane & 3) * 2;
            uint32_t af[2][4];
#pragma unroll
            for (int mt = 0; mt < 2; mt++) {
                int row = wm + mt * 16 + (lane >> 2);
                af[mt][0] = *(const uint32_t*)(Asb + row * GS + c);
                af[mt][1] = *(const uint32_t*)(Asb + (row + 8) * GS + c);
                af[mt][2] = *(const uint32_t*)(Asb + row * GS + c + 8);
                af[mt][3] = *(const uint32_t*)(Asb + (row + 8) * GS + c + 8);
            }
#pragma unroll
            for (int nt = 0; nt < 8; nt++) {
                int col = wn + nt * 8 + (lane >> 2);
                uint32_t b0 = *(const uint32_t*)(Bsb + col * GS + c);
                uint32_t b1 = *(const uint32_t*)(Bsb + col * GS + c + 8);
                mma16(acc[0][nt], af[0], b0, b1);
                mma16(acc[1][nt], af[1], b0, b1);
            }
        }

        if (more) {
            __half* Bsn = BsB + (p ^ 1) * GBUF;
#pragma unroll
            for (int it = 0; it < 4; it++) {
                int lin = tid + it * 256;
                int n = lin & 127, kb = (lin >> 7) * 4;
                *(uint2*)(Bsn + n * GS + kb) = rbp[it];
            }
        }
        CP_WAIT0();
        __syncthreads();
    }

    const float mul = (is_qkv && bcol < 512) ? qmul : 1.0f;
    if (half_out) {
        __half* C = (__half*)Cv;
#pragma unroll
        for (int mt = 0; mt < 2; mt++)
#pragma unroll
            for (int nt = 0; nt < 8; nt++) {
                int r = brow + wm + mt * 16 + (lane >> 2);
                int c = bcol + wn + nt * 8 + (lane & 3) * 2;
                *(uint32_t*)(C + (size_t)r * N + c) =
                    packf2(acc[mt][nt][0] * mul, acc[mt][nt][1] * mul);
                *(uint32_t*)(C + (size_t)(r + 8) * N + c) =
                    packf2(acc[mt][nt][2] * mul, acc[mt][nt][3] * mul);
            }
    } else {
        float* C = (float*)Cv;
#pragma unroll
        for (int mt = 0; mt < 2; mt++)
#pragma unroll
            for (int nt = 0; nt < 8; nt++) {
                int r = brow + wm + mt * 16 + (lane >> 2);
                int c = bcol + wn + nt * 8 + (lane & 3) * 2;
                *(float2*)(C + (size_t)r * N + c)       = make_float2(acc[mt][nt][0], acc[mt][nt][1]);
                *(float2*)(C + (size_t)(r + 8) * N + c) = make_float2(acc[mt][nt][2], acc[mt][nt][3]);
            }
    }
}

// ---------------------------------------------------------------------------
// Flash attention, all-half storage. Q pre-scaled by 0.125*log2e at GEMM.
// Block = 64 q rows of (b,h), 128 thr / 4 warps. K via cp.async, V transposed
// gather. Ones-column in Vt row 64 -> PV mma n-tile 8 accumulates l.
// ---------------------------------------------------------------------------
#define FS 72
#define KBUF (64 * FS)
#define VBUF (72 * FS)
#define FLASH_SMEM ((KBUF * 3 + VBUF * 2) * 2)   // Qs + 2K + 2Vt, bytes

__global__ void __launch_bounds__(128, 3) flash_h(
    const __half* __restrict__ qkv, const float* __restrict__ pos_bias,
    __half* __restrict__ O)
{
    const int qt = blockIdx.x, h = blockIdx.y, b = blockIdx.z;
    const int tid = threadIdx.x, lane = tid & 31, w = tid >> 5;
    const int q0 = qt * 64;

    if (g_focus[b]) {
#pragma unroll
        for (int it = 0; it < 4; it++) {
            int lin = tid + it * 128;
            int r = lin >> 3, cs = (lin & 7) * 8;
            const uint4 v = *(const uint4*)(qkv + (size_t)(b * Nn + q0 + r) * 1536
                                            + 1024 + h * DHn + cs);
            *(uint4*)(O + (size_t)(b * Nn + q0 + r) * HIDn + h * DHn + cs) = v;
        }
        return;
    }

    extern __shared__ __half smh[];
    __half* Qs  = smh;                 // 64 x 72
    __half* KsB = smh + KBUF;          // 2 x (64 x 72)  [key][d]
    __half* VtB = smh + 3 * KBUF;      // 2 x (72 x 72)  [d][key], row 64 = ones

    const size_t bN = (size_t)b * Nn;

    // ---- prologue ----
    // K tile 0 via cp.async (8B chunks)
#pragma unroll
    for (int it = 0; it < 8; it++) {
        int lin = tid + it * 128;
        int r = lin >> 4, c4 = (lin & 15) * 4;
        cpa8(KsB + r * FS + c4, qkv + (bN + r) * 1536 + 512 + h * DHn + c4);
    }
    CP_COMMIT();
    // Q tile (pre-scaled at GEMM): uint4 load, 2x uint2 store
#pragma unroll
    for (int it = 0; it < 4; it++) {
        int lin = tid + it * 128;
        int r = lin >> 3, cs = (lin & 7) * 8;
        uint4 q4 = *(const uint4*)(qkv + (bN + q0 + r) * 1536 + h * DHn + cs);
        *(uint2*)(Qs + r * FS + cs)     = make_uint2(q4.x, q4.y);
        *(uint2*)(Qs + r * FS + cs + 4) = make_uint2(q4.z, q4.w);
    }
    // V tile 0 (transposed gather) + ones rows for both buffers
#pragma unroll
    for (int it = 0; it < 8; it++) {
        int lin = tid + it * 128;
        int d = lin & 63, kq = (lin >> 6) * 4;
        const __half* vb = qkv + (bN + kq) * 1536 + 1024 + h * DHn + d;
        *(uint2*)(VtB + d * FS + kq) =
            make_uint2(packh2(vb[0], vb[1536]), packh2(vb[2 * 1536], vb[3 * 1536]));
    }
    {
        // rows 64..71: row 64 = 1.0, rows 65..71 = 0 (both buffers, keys 0..63)
        const __half one = __float2half(1.0f), zero = __float2half(0.0f);
#pragma unroll
        for (int it = 0; it < 8; it++) {
            int lin = tid + it * 128;                 // 1024 slots
            int buf = lin >> 9;                       // 0/1
            int rr  = (lin >> 6) & 7;                 // 0..7
            int key = lin & 63;
            VtB[buf * VBUF + (64 + rr) * FS + key] = (rr == 0) ? one : zero;
        }
    }
    CP_WAIT0();
    __syncthreads();

    // Q fragments (A operand)
    uint32_t aq[4][4];
    {
        const int r0 = w * 16 + (lane >> 2);
#pragma unroll
        for (int kc = 0; kc < 4; kc++) {
            int c = kc * 16 + (lane & 3) * 2;
            aq[kc][0] = *(const uint32_t*)(Qs + r0 * FS + c);
            aq[kc][1] = *(const uint32_t*)(Qs + (r0 + 8) * FS + c);
            aq[kc][2] = *(const uint32_t*)(Qs + r0 * FS + c + 8);
            aq[kc][3] = *(const uint32_t*)(Qs + (r0 + 8) * FS + c + 8);
        }
    }

    float o[9][4];                 // nt 8 = l accumulator (ones column)
#pragma unroll
    for (int nt = 0; nt < 9; nt++)
#pragma unroll
        for (int i = 0; i < 4; i++) o[nt][i] = 0.f;
    float m0 = -1e30f, m1 = -1e30f;

    const float* pbbase = pos_bias + ((size_t)h * Nn + (q0 + w * 16 + (lane >> 2))) * Nn
                          + 2 * (lane & 3);

    uint2 vreg[8];

    for (int kt = 0; kt < Nn / 64; kt++) {
        const int p  = kt & 1;
        const int k0 = kt * 64;
        const bool more = (kt + 1 < Nn / 64);

        // (A) next K tile via cp.async
        if (more) {
            const int kn = k0 + 64;
#pragma unroll
            for (int it = 0; it < 8; it++) {
                int lin = tid + it * 128;
                int r = lin >> 4, c4 = (lin & 15) * 4;
                cpa8(KsB + (p ^ 1) * KBUF + r * FS + c4,
                     qkv + (bN + kn + r) * 1536 + 512 + h * DHn + c4);
            }
        }
        CP_COMMIT();

        const __half* Ksb = KsB + p * KBUF;
        const __half* Vtb = VtB + p * VBUF;

        // (B) S = Q @ K^T (log2 units)
        float s[8][4];
#pragma unroll
        for (int nt = 0; nt < 8; nt++)
#pragma unroll
            for (int i = 0; i < 4; i++) s[nt][i] = 0.f;
#pragma unroll
        for (int kc = 0; kc < 4; kc++) {
            const int c = kc * 16 + (lane & 3) * 2;
#pragma unroll
            for (int nt = 0; nt < 8; nt++) {
                int kr = nt * 8 + (lane >> 2);
                uint32_t b0 = *(const uint32_t*)(Ksb + kr * FS + c);
                uint32_t b1 = *(const uint32_t*)(Ksb + kr * FS + c + 8);
                mma16(s[nt], aq[kc], b0, b1);
            }
        }

        // (C) + pos_bias * log2e; online max
        const float* pb0 = pbbase + k0;
        const float* pb1 = pb0 + 8 * Nn;
#pragma unroll
        for (int nt = 0; nt < 8; nt++) {
            float2 x0 = *(const float2*)(pb0 + nt * 8);
            float2 x1 = *(const float2*)(pb1 + nt * 8);
            s[nt][0] = fmaf(x0.x, L2E, s[nt][0]);
            s[nt][1] = fmaf(x0.y, L2E, s[nt][1]);
            s[nt][2] = fmaf(x1.x, L2E, s[nt][2]);
            s[nt][3] = fmaf(x1.y, L2E, s[nt][3]);
        }
        float rmax0 = -1e30f, rmax1 = -1e30f;
#pragma unroll
        for (int nt = 0; nt < 8; nt++) {
            rmax0 = fmaxf(rmax0, fmaxf(s[nt][0], s[nt][1]));
            rmax1 = fmaxf(rmax1, fmaxf(s[nt][2], s[nt][3]));
        }
#pragma unroll
        for (int off = 1; off <= 2; off <<= 1) {
            rmax0 = fmaxf(rmax0, __shfl_xor_sync(0xffffffffu, rmax0, off));
            rmax1 = fmaxf(rmax1, __shfl_xor_sync(0xffffffffu, rmax1, off));
        }
        float mn0 = fmaxf(m0, rmax0), mn1 = fmaxf(m1, rmax1);
        float corr0 = ex2f(m0 - mn0), corr1 = ex2f(m1 - mn1);
        m0 = mn0; m1 = mn1;
#pragma unroll
        for (int nt = 0; nt < 9; nt++) {       // includes l accumulator
            o[nt][0] *= corr0; o[nt][1] *= corr0;
            o[nt][2] *= corr1; o[nt][3] *= corr1;
        }

        // (D) P = ex2(s - mn) directly in half2 (A-operand layout)
        uint32_t pa[4][4];
#pragma unroll
        for (int kc = 0; kc < 4; kc++) {
            pa[kc][0] = ex2h2(s[2 * kc][0]     - mn0, s[2 * kc][1]     - mn0);
            pa[kc][1] = ex2h2(s[2 * kc][2]     - mn1, s[2 * kc][3]     - mn1);
            pa[kc][2] = ex2h2(s[2 * kc + 1][0] - mn0, s[2 * kc + 1][1] - mn0);
            pa[kc][3] = ex2h2(s[2 * kc + 1][2] - mn1, s[2 * kc + 1][3] - mn1);
        }

        // (E) next V gather (hide LDG under PV mma)
        if (more) {
            const int kn = k0 + 64;
#pragma unroll
            for (int it = 0; it < 8; it++) {
                int lin = tid + it * 128;
                int d = lin & 63, kq = (lin >> 6) * 4;
                const __half* vb = qkv + (bN + kn + kq) * 1536 + 1024 + h * DHn + d;
                vreg[it] = make_uint2(packh2(vb[0], vb[1536]),
                                      packh2(vb[2 * 1536], vb[3 * 1536]));
            }
        }

        // (F) O += P @ Vt  (9 n-tiles; tile 8 = ones column -> l)
#pragma unroll
        for (int kc = 0; kc < 4; kc++) {
            const int c = kc * 16 + (lane & 3) * 2;
#pragma unroll
            for (int nt = 0; nt < 9; nt++) {
                int vd = nt * 8 + (lane >> 2);
                uint32_t b0 = *(const uint32_t*)(Vtb + vd * FS + c);
                uint32_t b1 = *(const uint32_t*)(Vtb + vd * FS + c + 8);
                mma16(o[nt], pa[kc], b0, b1);
            }
        }

        // (G) store next V tile (transposed)
        if (more) {
            __half* Vtn = VtB + (p ^ 1) * VBUF;
#pragma unroll
            for (int it = 0; it < 8; it++) {
                int lin = tid + it * 128;
                int d = lin & 63, kq = (lin >> 6) * 4;
                *(uint2*)(Vtn + d * FS + kq) = vreg[it];
            }
        }
        CP_WAIT0();
        __syncthreads();
    }

    // l from ones column (lane&3 == 0 holds it in elems 0/2)
    float l0 = __shfl_sync(0xffffffffu, o[8][0], lane & 28);
    float l1 = __shfl_sync(0xffffffffu, o[8][2], lane & 28);
    float inv0 = 1.f / l0, inv1 = 1.f / l1;

    int gr = b * Nn + q0 + w * 16 + (lane >> 2);
    __half* op = O + (size_t)gr * HIDn + h * DHn + 2 * (lane & 3);
#pragma unroll
    for (int nt = 0; nt < 8; nt++) {
        *(uint32_t*)(op + nt * 8)            = packf2(o[nt][0] * inv0, o[nt][1] * inv0);
        *(uint32_t*)(op + 8 * HIDn + nt * 8) = packf2(o[nt][2] * inv1, o[nt][3] * inv1);
    }
}

// ---------------------------------------------------------------------------
extern "C" void kernel_launch(void* const* d_in, const int* in_sizes, int n_in,
                              void* d_out, int out_size)
{
    const float*         x        = (const float*)d_in[0];
    const float*         pos_bias = (const float*)d_in[1];
    const unsigned char* maskp    = (const unsigned char*)d_in[2];
    const float*         w_qkv    = (const float*)d_in[3];
    const float*         w_out    = (const float*)d_in[4];
    float*               out      = (float*)d_out;

    __half *xh, *wqkvh, *wouth, *qkvh, *oh;
    cudaGetSymbolAddress((void**)&xh,    g_xh);
    cudaGetSymbolAddress((void**)&wqkvh, g_wqkvh);
    cudaGetSymbolAddress((void**)&wouth, g_wouth);
    cudaGetSymbolAddress((void**)&qkvh,  g_qkvh);
    cudaGetSymbolAddress((void**)&oh,    g_oh);

    cudaFuncSetAttribute(gemm_h,  cudaFuncAttributeMaxDynamicSharedMemorySize, GEMM_SMEM);
    cudaFuncSetAttribute(flash_h, cudaFuncAttributeMaxDynamicSharedMemorySize, FLASH_SMEM);

    decode_mask_kernel<<<1, 1>>>(maskp);

    // converts (fp32 -> fp16)
    f2h_kernel<<<(Bn * Nn * 512 / 4 + 255) / 256, 256>>>((const float4*)x, (uint2*)xh,
                                                         Bn * Nn * 512 / 4);
    f2h_kernel<<<(512 * 1536 / 4 + 255) / 256, 256>>>((const float4*)w_qkv, (uint2*)wqkvh,
                                                      512 * 1536 / 4);
    f2h_kernel<<<(512 * 512 / 4 + 255) / 256, 256>>>((const float4*)w_out, (uint2*)wouth,
                                                     512 * 512 / 4);

    // qkv = x @ w_qkv  (half out; q cols pre-scaled by 0.125*log2e; focus skip)
    gemm_h<<<dim3(12, 64), 256, GEMM_SMEM>>>(8192, 1536, 512, xh, wqkvh, qkvh,
                                             1, QSCALEC, 1);

    // fused flash attention (half in/out)
    flash_h<<<dim3(Nn / 64, HEADSn, Bn), 128, FLASH_SMEM>>>(qkvh, pos_bias, oh);

    // out = O @ w_out (float out)
    gemm_h<<<dim3(4, 64), 256, GEMM_SMEM>>>(8192, 512, 512, oh, wouth, out,
                                            0, 1.0f, 0);
}

// round 6
// speedup vs baseline: 5.1634x; 1.2656x over previous
#include <cuda_runtime.h>
#include <cuda_fp16.h>
#include <stdint.h>

#define Bn    4
#define Nn    2048
#define HEADSn 8
#define DHn   64
#define HIDn  512
#define L2E   1.4426950408889634f
#define QSCALEC (0.125f * 1.4426950408889634f)

// Scratch (device globals; allocation-free rule)
__device__ __half g_xh   [Bn * Nn * 512];
__device__ __half g_wqkvh[512 * 1536];
__device__ __half g_wouth[512 * 512];
__device__ __half g_qkvh [Bn * Nn * 1536];   // q|k|v halves (q pre-scaled)
__device__ __half g_oh   [Bn * Nn * 512];
__device__ int    g_focus[Bn];

// ---------------------------------------------------------------------------
__device__ __forceinline__ float ex2f(float x) {
    float r; asm("ex2.approx.ftz.f32 %0, %1;" : "=f"(r) : "f"(x)); return r;
}
__device__ __forceinline__ uint32_t ex2h2(float a, float b) {
    __half2 h = __floats2half2_rn(a, b);
    uint32_t u = *reinterpret_cast<uint32_t*>(&h);
    asm("ex2.approx.f16x2 %0, %0;" : "+r"(u));
    return u;
}
__device__ __forceinline__ uint32_t packf2(float a, float b) {
    __half2 h = __floats2half2_rn(a, b);
    return *reinterpret_cast<uint32_t*>(&h);
}
__device__ __forceinline__ void mma16(float* d, const uint32_t* a, uint32_t b0, uint32_t b1) {
    asm volatile(
        "mma.sync.aligned.m16n8k16.row.col.f32.f16.f16.f32 "
        "{%0,%1,%2,%3}, {%4,%5,%6,%7}, {%8,%9}, {%0,%1,%2,%3};"
        : "+f"(d[0]), "+f"(d[1]), "+f"(d[2]), "+f"(d[3])
        : "r"(a[0]), "r"(a[1]), "r"(a[2]), "r"(a[3]), "r"(b0), "r"(b1));
}
__device__ __forceinline__ void ldsm4(uint32_t& r0, uint32_t& r1, uint32_t& r2, uint32_t& r3,
                                      uint32_t a) {
    asm volatile("ldmatrix.sync.aligned.m8n8.x4.shared.b16 {%0,%1,%2,%3}, [%4];"
        : "=r"(r0), "=r"(r1), "=r"(r2), "=r"(r3) : "r"(a));
}
__device__ __forceinline__ void ldsm4t(uint32_t& r0, uint32_t& r1, uint32_t& r2, uint32_t& r3,
                                       uint32_t a) {
    asm volatile("ldmatrix.sync.aligned.m8n8.x4.trans.shared.b16 {%0,%1,%2,%3}, [%4];"
        : "=r"(r0), "=r"(r1), "=r"(r2), "=r"(r3) : "r"(a));
}
__device__ __forceinline__ void ldsm2t(uint32_t& r0, uint32_t& r1, uint32_t a) {
    asm volatile("ldmatrix.sync.aligned.m8n8.x2.trans.shared.b16 {%0,%1}, [%2];"
        : "=r"(r0), "=r"(r1) : "r"(a));
}
__device__ __forceinline__ void cpa16(void* s, const void* g) {
    uint32_t sa = (uint32_t)__cvta_generic_to_shared(s);
    asm volatile("cp.async.ca.shared.global [%0], [%1], 16;" :: "r"(sa), "l"(g));
}
#define CP_COMMIT() asm volatile("cp.async.commit_group;")
#define CP_WAIT0()  asm volatile("cp.async.wait_group 0;")

// ---------------------------------------------------------------------------
__global__ void decode_mask_kernel(const unsigned char* __restrict__ p) {
    unsigned int w[4];
#pragma unroll
    for (int i = 0; i < 4; i++) w[i] = ((const unsigned int*)p)[i];
    bool allF = true, allI = true, anyNZ = false;
#pragma unroll
    for (int i = 0; i < 4; i++) {
        if (w[i] != 0u) anyNZ = true;
        if (w[i] != 0u && w[i] != 0x3F800000u) allF = false;
        if (w[i] > 1u) allI = false;
    }
    if (anyNZ && allF)      for (int i = 0; i < 4; i++) g_focus[i] = (w[i] == 0x3F800000u);
    else if (allI)          for (int i = 0; i < 4; i++) g_focus[i] = (int)w[i];
    else                    for (int i = 0; i < 4; i++) g_focus[i] = p[i] ? 1 : 0;
}

__global__ void f2h_kernel(const float4* __restrict__ src, uint2* __restrict__ dst, int n4) {
    int i = blockIdx.x * blockDim.x + threadIdx.x;
    if (i < n4) {
        float4 v = src[i];
        dst[i] = make_uint2(packf2(v.x, v.y), packf2(v.z, v.w));
    }
}

// ---------------------------------------------------------------------------
// half GEMM: C(MxN) = A(MxK) @ B(KxN). 128x128x32 tiles, double-buffered,
// all-cp.async loads, ldmatrix fragments. 256 thr / 8 warps (4m x 2n).
// As: [m][k] stride 40. Bs: [k][n] stride 136 (trans ldmatrix for B frags).
// ---------------------------------------------------------------------------
#define GS 40
#define BSs 136
#define GABUF (128 * GS)     // halves
#define GBBUF (32 * BSs)     // halves
#define GEMM_SMEM ((2 * GABUF + 2 * GBBUF) * 2)

__global__ void __launch_bounds__(256, 2) gemm_h(
    int M, int N, int K,
    const __half* __restrict__ A, const __half* __restrict__ B, void* __restrict__ Cv,
    int is_qkv, float qmul, int half_out)
{
    extern __shared__ __half smh[];
    __half* AsB = smh;
    __half* BsB = smh + 2 * GABUF;

    const int tid  = threadIdx.x;
    const int lane = tid & 31;
    const int w    = tid >> 5;
    const int wm   = (w >> 1) * 32;
    const int wn   = (w & 1) * 64;
    const int brow = blockIdx.y * 128;
    const int bcol = blockIdx.x * 128;

    if (is_qkv && (bcol + 128 <= 1024) && g_focus[brow >> 11]) return;

    const uint32_t as_u = (uint32_t)__cvta_generic_to_shared(AsB);
    const uint32_t bs_u = (uint32_t)__cvta_generic_to_shared(BsB);

    // lane constants for A-type / trans-B ldmatrix
    const int rA = ((lane >> 3) & 1) * 8 + (lane & 7);
    const int cA = (lane >> 4) * 8;
    const uint32_t a_frag = as_u + ((wm + rA) * GS + cA) * 2;             // + mt*16*GS*2 + kc*32
    const uint32_t b_frag = bs_u + (rA * BSs + wn + cA) * 2;              // + kc*16*BSs*2 + ntp*32

    float acc[2][8][4];
#pragma unroll
    for (int mt = 0; mt < 2; mt++)
#pragma unroll
        for (int nt = 0; nt < 8; nt++)
#pragma unroll
            for (int i = 0; i < 4; i++) acc[mt][nt][i] = 0.f;

    const int nk = K / 32;

    // prologue: stage 0
#pragma unroll
    for (int it = 0; it < 2; it++) {
        int lin = tid + it * 256;
        int r = lin >> 2, c = (lin & 3) * 8;
        cpa16(AsB + r * GS + c, A + (size_t)(brow + r) * K + c);
        int rb = lin >> 4, cb = (lin & 15) * 8;
        cpa16(BsB + rb * BSs + cb, B + (size_t)rb * N + bcol + cb);
    }
    CP_COMMIT();
    CP_WAIT0();
    __syncthreads();

    for (int kt = 0; kt < nk; kt++) {
        const int p   = kt & 1;
        const int k0n = (kt + 1) * 32;
        const bool more = (kt + 1 < nk);

        if (more) {
#pragma unroll
            for (int it = 0; it < 2; it++) {
                int lin = tid + it * 256;
                int r = lin >> 2, c = (lin & 3) * 8;
                cpa16(AsB + (p ^ 1) * GABUF + r * GS + c,
                      A + (size_t)(brow + r) * K + k0n + c);
                int rb = lin >> 4, cb = (lin & 15) * 8;
                cpa16(BsB + (p ^ 1) * GBBUF + rb * BSs + cb,
                      B + (size_t)(k0n + rb) * N + bcol + cb);
            }
        }
        CP_COMMIT();

        const uint32_t af_b = a_frag + p * (GABUF * 2);
        const uint32_t bf_b = b_frag + p * (GBBUF * 2);
#pragma unroll
        for (int kc = 0; kc < 2; kc++) {
            uint32_t af[2][4];
            ldsm4(af[0][0], af[0][1], af[0][2], af[0][3], af_b + kc * 32);
            ldsm4(af[1][0], af[1][1], af[1][2], af[1][3], af_b + kc * 32 + 16 * GS * 2);
            const uint32_t bk = bf_b + kc * (16 * BSs * 2);
#pragma unroll
            for (int ntp = 0; ntp < 4; ntp++) {
                uint32_t b0, b1, b2, b3;
                ldsm4t(b0, b1, b2, b3, bk + ntp * 32);
                mma16(acc[0][2 * ntp],     af[0], b0, b1);
                mma16(acc[0][2 * ntp + 1], af[0], b2, b3);
                mma16(acc[1][2 * ntp],     af[1], b0, b1);
                mma16(acc[1][2 * ntp + 1], af[1], b2, b3);
            }
        }
        CP_WAIT0();
        __syncthreads();
    }

    const float mul = (is_qkv && bcol < 512) ? qmul : 1.0f;
    if (half_out) {
        __half* C = (__half*)Cv;
#pragma unroll
        for (int mt = 0; mt < 2; mt++)
#pragma unroll
            for (int nt = 0; nt < 8; nt++) {
                int r = brow + wm + mt * 16 + (lane >> 2);
                int c = bcol + wn + nt * 8 + (lane & 3) * 2;
                *(uint32_t*)(C + (size_t)r * N + c) =
                    packf2(acc[mt][nt][0] * mul, acc[mt][nt][1] * mul);
                *(uint32_t*)(C + (size_t)(r + 8) * N + c) =
                    packf2(acc[mt][nt][2] * mul, acc[mt][nt][3] * mul);
            }
    } else {
        float* C = (float*)Cv;
#pragma unroll
        for (int mt = 0; mt < 2; mt++)
#pragma unroll
            for (int nt = 0; nt < 8; nt++) {
                int r = brow + wm + mt * 16 + (lane >> 2);
                int c = bcol + wn + nt * 8 + (lane & 3) * 2;
                *(float2*)(C + (size_t)r * N + c)       = make_float2(acc[mt][nt][0], acc[mt][nt][1]);
                *(float2*)(C + (size_t)(r + 8) * N + c) = make_float2(acc[mt][nt][2], acc[mt][nt][3]);
            }
    }
}

// ---------------------------------------------------------------------------
// Flash attention. All tiles via cp.async in natural layout; fragments via
// ldmatrix (K: non-trans B; V: trans B; Q: A-type). V col 64 = ones -> PV mma
// accumulates softmax denominator. Base-2 softmax, Q pre-scaled.
// Block = 64 q rows of (b,h), 128 thr / 4 warps.
// ---------------------------------------------------------------------------
#define FS 72
#define FT (64 * FS)                 // halves per tile
#define FLASH_SMEM (5 * FT * 2)      // Qs + 2K + 2V

__global__ void __launch_bounds__(128, 3) flash_h(
    const __half* __restrict__ qkv, const float* __restrict__ pos_bias,
    __half* __restrict__ O)
{
    const int qt = blockIdx.x, h = blockIdx.y, b = blockIdx.z;
    const int tid = threadIdx.x, lane = tid & 31, w = tid >> 5;
    const int q0 = qt * 64;

    if (g_focus[b]) {
#pragma unroll
        for (int it = 0; it < 4; it++) {
            int lin = tid + it * 128;
            int r = lin >> 3, cs = (lin & 7) * 8;
            const uint4 v = *(const uint4*)(qkv + (size_t)(b * Nn + q0 + r) * 1536
                                            + 1024 + h * DHn + cs);
            *(uint4*)(O + (size_t)(b * Nn + q0 + r) * HIDn + h * DHn + cs) = v;
        }
        return;
    }

    extern __shared__ __half smh[];
    __half* Qs  = smh;               // 64 x 72
    __half* KsB = smh + FT;          // 2 x (64 x 72)  [key][d]
    __half* VsB = smh + 3 * FT;      // 2 x (64 x 72)  [key][d], col 64 = ones

    const size_t bN = (size_t)b * Nn;

    const uint32_t qs_u = (uint32_t)__cvta_generic_to_shared(Qs);
    const uint32_t ks_u = (uint32_t)__cvta_generic_to_shared(KsB);
    const uint32_t vs_u = (uint32_t)__cvta_generic_to_shared(VsB);

    // ---- prologue: Q, K0, V0 via cp.async ----
#pragma unroll
    for (int it = 0; it < 4; it++) {
        int lin = tid + it * 128;
        int r = lin >> 3, c = (lin & 7) * 8;
        cpa16(Qs  + r * FS + c, qkv + (bN + q0 + r) * 1536 + h * DHn + c);
        cpa16(KsB + r * FS + c, qkv + (bN + r) * 1536 + 512 + h * DHn + c);
        cpa16(VsB + r * FS + c, qkv + (bN + r) * 1536 + 1024 + h * DHn + c);
    }
    CP_COMMIT();
    // ones column (col 64 = 1, 65..71 = 0) for both V buffers
    {
        uint4 ones = make_uint4(0x00003C00u, 0u, 0u, 0u);
        int buf = tid >> 6, r = tid & 63;
        *(uint4*)(VsB + buf * FT + r * FS + 64) = ones;
    }
    CP_WAIT0();
    __syncthreads();

    // lane constants
    const int rA = ((lane >> 3) & 1) * 8 + (lane & 7);   // A-type / trans-B row
    const int cA = (lane >> 4) * 8;                      // A-type / trans-B col
    const int rB = (lane >> 4) * 8 + (lane & 7);         // non-trans B row
    const int cB = ((lane >> 3) & 1) * 8;                // non-trans B col

    // Q fragments (A operand) via ldmatrix
    uint32_t aq[4][4];
    {
        uint32_t qf = qs_u + ((w * 16 + rA) * FS + cA) * 2;
#pragma unroll
        for (int kc = 0; kc < 4; kc++)
            ldsm4(aq[kc][0], aq[kc][1], aq[kc][2], aq[kc][3], qf + kc * 32);
    }

    const uint32_t k_frag = ks_u + (rB * FS + cB) * 2;   // + p*FT*2 + ntp*16*FS*2 + kc*32
    const uint32_t v_frag = vs_u + (rA * FS + cA) * 2;   // + p*FT*2 + kc*16*FS*2 + ntp*32
    const uint32_t l_frag = vs_u + (rA * FS + 64) * 2;   // + p*FT*2 + kc*16*FS*2

    float o[9][4];
#pragma unroll
    for (int nt = 0; nt < 9; nt++)
#pragma unroll
        for (int i = 0; i < 4; i++) o[nt][i] = 0.f;
    float m0 = -1e30f, m1 = -1e30f;

    const float* pbbase = pos_bias + ((size_t)h * Nn + (q0 + w * 16 + (lane >> 2))) * Nn
                          + 2 * (lane & 3);

    for (int kt = 0; kt < Nn / 64; kt++) {
        const int p  = kt & 1;
        const int k0 = kt * 64;
        const bool more = (kt + 1 < Nn / 64);

        // prefetch next K,V tiles
        if (more) {
            const int kn = k0 + 64;
#pragma unroll
            for (int it = 0; it < 4; it++) {
                int lin = tid + it * 128;
                int r = lin >> 3, c = (lin & 7) * 8;
                cpa16(KsB + (p ^ 1) * FT + r * FS + c,
                      qkv + (bN + kn + r) * 1536 + 512 + h * DHn + c);
                cpa16(VsB + (p ^ 1) * FT + r * FS + c,
                      qkv + (bN + kn + r) * 1536 + 1024 + h * DHn + c);
            }
        }
        CP_COMMIT();

        // S = Q @ K^T
        float s[8][4];
#pragma unroll
        for (int nt = 0; nt < 8; nt++)
#pragma unroll
            for (int i = 0; i < 4; i++) s[nt][i] = 0.f;
        {
            const uint32_t kb = k_frag + p * (FT * 2);
#pragma unroll
            for (int kc = 0; kc < 4; kc++) {
#pragma unroll
                for (int ntp = 0; ntp < 4; ntp++) {
                    uint32_t b0, b1, b2, b3;
                    ldsm4(b0, b1, b2, b3, kb + ntp * (16 * FS * 2) + kc * 32);
                    mma16(s[2 * ntp],     aq[kc], b0, b1);
                    mma16(s[2 * ntp + 1], aq[kc], b2, b3);
                }
            }
        }

        // + pos_bias * log2e; online max
        const float* pb0 = pbbase + k0;
        const float* pb1 = pb0 + 8 * Nn;
#pragma unroll
        for (int nt = 0; nt < 8; nt++) {
            float2 x0 = *(const float2*)(pb0 + nt * 8);
            float2 x1 = *(const float2*)(pb1 + nt * 8);
            s[nt][0] = fmaf(x0.x, L2E, s[nt][0]);
            s[nt][1] = fmaf(x0.y, L2E, s[nt][1]);
            s[nt][2] = fmaf(x1.x, L2E, s[nt][2]);
            s[nt][3] = fmaf(x1.y, L2E, s[nt][3]);
        }
        float rmax0 = -1e30f, rmax1 = -1e30f;
#pragma unroll
        for (int nt = 0; nt < 8; nt++) {
            rmax0 = fmaxf(rmax0, fmaxf(s[nt][0], s[nt][1]));
            rmax1 = fmaxf(rmax1, fmaxf(s[nt][2], s[nt][3]));
        }
#pragma unroll
        for (int off = 1; off <= 2; off <<= 1) {
            rmax0 = fmaxf(rmax0, __shfl_xor_sync(0xffffffffu, rmax0, off));
            rmax1 = fmaxf(rmax1, __shfl_xor_sync(0xffffffffu, rmax1, off));
        }
        float mn0 = fmaxf(m0, rmax0), mn1 = fmaxf(m1, rmax1);
        float corr0 = ex2f(m0 - mn0), corr1 = ex2f(m1 - mn1);
        m0 = mn0; m1 = mn1;
#pragma unroll
        for (int nt = 0; nt < 9; nt++) {
            o[nt][0] *= corr0; o[nt][1] *= corr0;
            o[nt][2] *= corr1; o[nt][3] *= corr1;
        }

        // P = ex2(s - mn) in half2 (A-operand layout)
        uint32_t pa[4][4];
#pragma unroll
        for (int kc = 0; kc < 4; kc++) {
            pa[kc][0] = ex2h2(s[2 * kc][0]     - mn0, s[2 * kc][1]     - mn0);
            pa[kc][1] = ex2h2(s[2 * kc][2]     - mn1, s[2 * kc][3]     - mn1);
            pa[kc][2] = ex2h2(s[2 * kc + 1][0] - mn0, s[2 * kc + 1][1] - mn0);
            pa[kc][3] = ex2h2(s[2 * kc + 1][2] - mn1, s[2 * kc + 1][3] - mn1);
        }

        // O += P @ V  (trans ldmatrix from [key][d]); l via ones column
        {
            const uint32_t vb = v_frag + p * (FT * 2);
            const uint32_t lb = l_frag + p * (FT * 2);
#pragma unroll
            for (int kc = 0; kc < 4; kc++) {
                const uint32_t vk = vb + kc * (16 * FS * 2);
#pragma unroll
                for (int ntp = 0; ntp < 4; ntp++) {
                    uint32_t b0, b1, b2, b3;
                    ldsm4t(b0, b1, b2, b3, vk + ntp * 32);
                    mma16(o[2 * ntp],     pa[kc], b0, b1);
                    mma16(o[2 * ntp + 1], pa[kc], b2, b3);
                }
                uint32_t lb0, lb1;
                ldsm2t(lb0, lb1, lb + kc * (16 * FS * 2));
                mma16(o[8], pa[kc], lb0, lb1);
            }
        }
        CP_WAIT0();
        __syncthreads();
    }

    // l from ones column (lane&3==0 holds it in elems 0/2)
    float l0 = __shfl_sync(0xffffffffu, o[8][0], lane & 28);
    float l1 = __shfl_sync(0xffffffffu, o[8][2], lane & 28);
    float inv0 = 1.f / l0, inv1 = 1.f / l1;

    int gr = b * Nn + q0 + w * 16 + (lane >> 2);
    __half* op = O + (size_t)gr * HIDn + h * DHn + 2 * (lane & 3);
#pragma unroll
    for (int nt = 0; nt < 8; nt++) {
        *(uint32_t*)(op + nt * 8)            = packf2(o[nt][0] * inv0, o[nt][1] * inv0);
        *(uint32_t*)(op + 8 * HIDn + nt * 8) = packf2(o[nt][2] * inv1, o[nt][3] * inv1);
    }
}

// ---------------------------------------------------------------------------
extern "C" void kernel_launch(void* const* d_in, const int* in_sizes, int n_in,
                              void* d_out, int out_size)
{
    const float*         x        = (const float*)d_in[0];
    const float*         pos_bias = (const float*)d_in[1];
    const unsigned char* maskp    = (const unsigned char*)d_in[2];
    const float*         w_qkv    = (const float*)d_in[3];
    const float*         w_out    = (const float*)d_in[4];
    float*               out      = (float*)d_out;

    __half *xh, *wqkvh, *wouth, *qkvh, *oh;
    cudaGetSymbolAddress((void**)&xh,    g_xh);
    cudaGetSymbolAddress((void**)&wqkvh, g_wqkvh);
    cudaGetSymbolAddress((void**)&wouth, g_wouth);
    cudaGetSymbolAddress((void**)&qkvh,  g_qkvh);
    cudaGetSymbolAddress((void**)&oh,    g_oh);

    cudaFuncSetAttribute(gemm_h,  cudaFuncAttributeMaxDynamicSharedMemorySize, GEMM_SMEM);
    cudaFuncSetAttribute(flash_h, cudaFuncAttributeMaxDynamicSharedMemorySize, FLASH_SMEM);

    decode_mask_kernel<<<1, 1>>>(maskp);

    f2h_kernel<<<(Bn * Nn * 512 / 4 + 255) / 256, 256>>>((const float4*)x, (uint2*)xh,
                                                         Bn * Nn * 512 / 4);
    f2h_kernel<<<(512 * 1536 / 4 + 255) / 256, 256>>>((const float4*)w_qkv, (uint2*)wqkvh,
                                                      512 * 1536 / 4);
    f2h_kernel<<<(512 * 512 / 4 + 255) / 256, 256>>>((const float4*)w_out, (uint2*)wouth,
                                                     512 * 512 / 4);

    // qkv = x @ w_qkv  (half out; q cols pre-scaled; focus q/k skip)
    gemm_h<<<dim3(12, 64), 256, GEMM_SMEM>>>(8192, 1536, 512, xh, wqkvh, qkvh,
                                             1, QSCALEC, 1);

    // fused flash attention
    flash_h<<<dim3(Nn / 64, HEADSn, Bn), 128, FLASH_SMEM>>>(qkvh, pos_bias, oh);

    // out = O @ w_out (float out)
    gemm_h<<<dim3(4, 64), 256, GEMM_SMEM>>>(8192, 512, 512, oh, wouth, out,
                                            0, 1.0f, 0);
}